// round 6
// baseline (speedup 1.0000x reference)
#include <cuda_runtime.h>
#include <cuda_bf16.h>
#include <math.h>

// ---------------------------------------------------------------------------
// FrameTransformerDecoder — fp32 baseline
// Shapes: B=1, C=8, OC=8, F=1024, W=512, H=8, d=128, EXP=4
// Outputs (concatenated in d_out): x+z (8*1024*512), pq1 (64*512*512), pq2 (64*512*512)
// ---------------------------------------------------------------------------

#define F_DIM 1024
#define W_DIM 512
#define FW    (F_DIM * W_DIM)          // 524288
#define NINST 64                        // OC(8) * H(8)
#define QKSZ  (W_DIM * W_DIM)           // 262144 per instance
#define LOG2E 1.4426950408889634f
#define QK_SCALE 0.0883883476483184f    // 1/sqrt(128)

// ------------------------- scratch (device globals) ------------------------
__device__ float g_nx [8  * FW];
__device__ float g_q  [8  * FW];
__device__ float g_k  [8  * FW];
__device__ float g_v  [8  * FW];
__device__ float g_vt [NINST * W_DIM * 128];
__device__ float g_att[8  * FW];
__device__ float g_z1 [8  * FW];
__device__ float g_z2 [8  * FW];
__device__ float g_nh [16 * FW];
__device__ float g_n3 [24 * FW];
__device__ float g_t  [32 * FW];
__device__ float g_rm [NINST * W_DIM];
__device__ float g_rs [NINST * W_DIM];

// ------------------------------ LayerNorm ----------------------------------
// Normalizes over F (1024) per (c, w). Channel c gathered from up to 3 sources
// (concat emulation). grid = (W/128, C), block = 128.
__global__ __launch_bounds__(128)
void ln_kernel(const float* s0, const float* s1, const float* s2,
               const float* __restrict__ g, const float* __restrict__ b,
               float* __restrict__ out)
{
    int c = blockIdx.y;
    int w = blockIdx.x * 128 + threadIdx.x;
    const float* src = (c < 8) ? (s0 + c * FW)
                     : (c < 16) ? (s1 + (c - 8) * FW)
                                : (s2 + (c - 16) * FW);
    const float* p = src + w;
    float sum = 0.f, sq = 0.f;
    #pragma unroll 4
    for (int f = 0; f < F_DIM; f++) {
        float v = p[f * W_DIM];
        sum += v;
        sq = fmaf(v, v, sq);
    }
    float mu  = sum * (1.f / 1024.f);
    float var = sq * (1.f / 1024.f) - mu * mu;
    float inv = rsqrtf(var + 1e-8f);
    float* op = out + c * FW + w;
    const float* gp = g + c * F_DIM;
    const float* bp = b + c * F_DIM;
    #pragma unroll 4
    for (int f = 0; f < F_DIM; f++) {
        float v = p[f * W_DIM];
        op[f * W_DIM] = (v - mu) * inv * gp[f] + bp[f];
    }
}

// ------------------------------ 1x3 conv -----------------------------------
// out[o,f,w] = sum_{ic,t} in[ic,f,w+t-1] * wgt[(o*IC+ic)*3+t], OC = 8.
// grid = 2048, block = 256.
__global__ __launch_bounds__(256)
void conv1x3_kernel(const float* __restrict__ in, const float* __restrict__ wgt,
                    float* __restrict__ out, int IC)
{
    __shared__ float ws[8 * 16 * 3];
    int nw = 8 * IC * 3;
    for (int e = threadIdx.x; e < nw; e += 256) ws[e] = wgt[e];
    __syncthreads();

    int p = blockIdx.x * 256 + threadIdx.x;
    int f = p >> 9, w = p & 511;
    float acc[8] = {0.f, 0.f, 0.f, 0.f, 0.f, 0.f, 0.f, 0.f};
    for (int ic = 0; ic < IC; ic++) {
        const float* bp = in + (ic * F_DIM + f) * W_DIM + w;
        float m = bp[0];
        float l = (w > 0)   ? bp[-1] : 0.f;
        float r = (w < 511) ? bp[1]  : 0.f;
        #pragma unroll
        for (int o = 0; o < 8; o++) {
            const float* wp = ws + (o * IC + ic) * 3;
            acc[o] = fmaf(l, wp[0], acc[o]);
            acc[o] = fmaf(m, wp[1], acc[o]);
            acc[o] = fmaf(r, wp[2], acc[o]);
        }
    }
    #pragma unroll
    for (int o = 0; o < 8; o++)
        out[(o * F_DIM + f) * W_DIM + w] = acc[o];
}

// --------------------------- V transpose -----------------------------------
// v[oc, h*128+dd, w] -> vt[inst][w][dd]. grid = (16, 4, 64), block = (32, 8).
__global__ __launch_bounds__(256)
void vtrans_kernel(const float* __restrict__ v, float* __restrict__ vt)
{
    __shared__ float tile[32][33];
    int i = blockIdx.z, oc = i >> 3, h = i & 7;
    const float* vb = v + (oc * F_DIM + h * 128) * W_DIM;
    float* ob = vt + i * (W_DIM * 128);
    int w0 = blockIdx.x * 32, d0 = blockIdx.y * 32;
    int tx = threadIdx.x, ty = threadIdx.y;
    #pragma unroll
    for (int j = ty; j < 32; j += 8)
        tile[j][tx] = vb[(d0 + j) * W_DIM + w0 + tx];
    __syncthreads();
    #pragma unroll
    for (int j = ty; j < 32; j += 8)
        ob[(w0 + j) * 128 + d0 + tx] = tile[tx][j];
}

// ------------------------------ QK GEMM ------------------------------------
// qk[i,q,k] = scale * sum_dd Q[dd,q]*K[dd,k] + b0 (+ b1) (+ b2) -> out
// grid = (8 ktiles, 8 qtiles, 64 inst), block = 256, 64x64 tile, BK = 8.
__global__ __launch_bounds__(256)
void qk_kernel(const float* __restrict__ q, const float* __restrict__ k,
               const float* __restrict__ b0, const float* __restrict__ b1,
               const float* __restrict__ b2, float* __restrict__ out)
{
    __shared__ __align__(16) float As[8][64];
    __shared__ __align__(16) float Bs[8][64];
    int i = blockIdx.z, oc = i >> 3, h = i & 7;
    const float* qb = q + (oc * F_DIM + h * 128) * W_DIM;
    const float* kb = k + (oc * F_DIM + h * 128) * W_DIM;
    int k0 = blockIdx.x * 64, q0 = blockIdx.y * 64;
    int t = threadIdx.x;
    int tx = t & 15, ty = t >> 4;
    float acc[4][4];
    #pragma unroll
    for (int u = 0; u < 4; u++)
        #pragma unroll
        for (int v = 0; v < 4; v++) acc[u][v] = 0.f;

    for (int d0 = 0; d0 < 128; d0 += 8) {
        int e0 = t, e1 = t + 256;
        As[e0 >> 6][e0 & 63] = qb[(d0 + (e0 >> 6)) * W_DIM + q0 + (e0 & 63)];
        Bs[e0 >> 6][e0 & 63] = kb[(d0 + (e0 >> 6)) * W_DIM + k0 + (e0 & 63)];
        As[e1 >> 6][e1 & 63] = qb[(d0 + (e1 >> 6)) * W_DIM + q0 + (e1 & 63)];
        Bs[e1 >> 6][e1 & 63] = kb[(d0 + (e1 >> 6)) * W_DIM + k0 + (e1 & 63)];
        __syncthreads();
        #pragma unroll
        for (int kk = 0; kk < 8; kk++) {
            float4 a4 = *(const float4*)&As[kk][ty * 4];
            float4 b4 = *(const float4*)&Bs[kk][tx * 4];
            float av[4] = {a4.x, a4.y, a4.z, a4.w};
            float bv[4] = {b4.x, b4.y, b4.z, b4.w};
            #pragma unroll
            for (int u = 0; u < 4; u++)
                #pragma unroll
                for (int v = 0; v < 4; v++)
                    acc[u][v] = fmaf(av[u], bv[v], acc[u][v]);
        }
        __syncthreads();
    }

    int ibase = i * QKSZ;
    #pragma unroll
    for (int u = 0; u < 4; u++) {
        int row = ibase + (q0 + ty * 4 + u) * W_DIM + k0 + tx * 4;
        float4 o4;
        o4.x = acc[u][0] * QK_SCALE;
        o4.y = acc[u][1] * QK_SCALE;
        o4.z = acc[u][2] * QK_SCALE;
        o4.w = acc[u][3] * QK_SCALE;
        float4 t0 = *(const float4*)(b0 + row);
        o4.x += t0.x; o4.y += t0.y; o4.z += t0.z; o4.w += t0.w;
        if (b1) {
            float4 t1 = *(const float4*)(b1 + row);
            o4.x += t1.x; o4.y += t1.y; o4.z += t1.z; o4.w += t1.w;
        }
        if (b2) {
            float4 t2 = *(const float4*)(b2 + row);
            o4.x += t2.x; o4.y += t2.y; o4.z += t2.z; o4.w += t2.w;
        }
        *(float4*)(out + row) = o4;
    }
}

// ---------------------------- softmax rowstats -----------------------------
// One warp per row of 512. grid = 4096, block = 256.
__global__ __launch_bounds__(256)
void rowstats_kernel(const float* __restrict__ qk, float* __restrict__ rm,
                     float* __restrict__ rs)
{
    int row  = blockIdx.x * 8 + (threadIdx.x >> 5);
    int lane = threadIdx.x & 31;
    const float4* p = (const float4*)(qk + row * W_DIM);
    float4 vals[4];
    float mx = -1e30f;
    #pragma unroll
    for (int j = 0; j < 4; j++) {
        float4 v = p[lane + j * 32];
        vals[j] = v;
        mx = fmaxf(mx, fmaxf(fmaxf(v.x, v.y), fmaxf(v.z, v.w)));
    }
    #pragma unroll
    for (int o = 16; o > 0; o >>= 1)
        mx = fmaxf(mx, __shfl_xor_sync(0xffffffffu, mx, o));
    float s = 0.f;
    #pragma unroll
    for (int j = 0; j < 4; j++) {
        float4 v = vals[j];
        s += exp2f((v.x - mx) * LOG2E) + exp2f((v.y - mx) * LOG2E)
           + exp2f((v.z - mx) * LOG2E) + exp2f((v.w - mx) * LOG2E);
    }
    #pragma unroll
    for (int o = 16; o > 0; o >>= 1)
        s += __shfl_xor_sync(0xffffffffu, s, o);
    if (lane == 0) { rm[row] = mx; rs[row] = 1.f / s; }
}

// ------------------------------ AV GEMM ------------------------------------
// a[q,dd] = sum_k softmax(qk)[q,k] * vt[k,dd]; store att[oc, h*128+dd, q].
// grid = (8 qtiles, 64 inst), block 256, tile 64q x 128dd, BK = 8.
__global__ __launch_bounds__(256)
void av_kernel(const float* __restrict__ qk, const float* __restrict__ rm,
               const float* __restrict__ rs, const float* __restrict__ vt,
               float* __restrict__ att)
{
    __shared__ __align__(16) float Ps[8][64];
    __shared__ __align__(16) float Vs[8][128];
    int i = blockIdx.y, oc = i >> 3, h = i & 7;
    int q0 = blockIdx.x * 64;
    const float* qkb = qk + i * QKSZ;
    const float* vb  = vt + i * (W_DIM * 128);
    float* ab = att + (oc * F_DIM + h * 128) * W_DIM;
    int t = threadIdx.x;
    int tx = t & 15, ty = t >> 4;

    int pe = t * 2, pqq = pe >> 3, pkk = pe & 7;
    float m  = rm[i * W_DIM + q0 + pqq];
    float si = rs[i * W_DIM + q0 + pqq];
    const float* prow = qkb + (q0 + pqq) * W_DIM + pkk;
    int ve = t * 4, vkk = ve >> 7, vdd = ve & 127;

    float acc[4][8];
    #pragma unroll
    for (int u = 0; u < 4; u++)
        #pragma unroll
        for (int v = 0; v < 8; v++) acc[u][v] = 0.f;

    for (int k0 = 0; k0 < 512; k0 += 8) {
        float v0 = prow[k0];
        float v1 = prow[k0 + 1];
        Ps[pkk][pqq]     = exp2f((v0 - m) * LOG2E) * si;
        Ps[pkk + 1][pqq] = exp2f((v1 - m) * LOG2E) * si;
        float4 vv4 = *(const float4*)&vb[(k0 + vkk) * 128 + vdd];
        *(float4*)&Vs[vkk][vdd] = vv4;
        __syncthreads();
        #pragma unroll
        for (int kk = 0; kk < 8; kk++) {
            float4 p4 = *(const float4*)&Ps[kk][ty * 4];
            float4 va = *(const float4*)&Vs[kk][tx * 8];
            float4 vb2 = *(const float4*)&Vs[kk][tx * 8 + 4];
            float pv[4] = {p4.x, p4.y, p4.z, p4.w};
            float vv[8] = {va.x, va.y, va.z, va.w, vb2.x, vb2.y, vb2.z, vb2.w};
            #pragma unroll
            for (int u = 0; u < 4; u++)
                #pragma unroll
                for (int v = 0; v < 8; v++)
                    acc[u][v] = fmaf(pv[u], vv[v], acc[u][v]);
        }
        __syncthreads();
    }

    #pragma unroll
    for (int v = 0; v < 8; v++) {
        int dd = tx * 8 + v;
        float4 o4 = make_float4(acc[0][v], acc[1][v], acc[2][v], acc[3][v]);
        *(float4*)&ab[dd * W_DIM + q0 + ty * 4] = o4;
    }
}

// --------------------- 3x3 conv 24->32 + SquaredReLU -----------------------
// grid = 2048, block = 256. Weights (32,24,3,3) OIHW -> smem [idx][oc].
__global__ __launch_bounds__(256)
void conv3x3_sq_kernel(const float* __restrict__ in, const float* __restrict__ wgt,
                       float* __restrict__ out)
{
    __shared__ __align__(16) float ws[216 * 32];
    for (int e = threadIdx.x; e < 216 * 32; e += 256) {
        int o = e & 31, idx = e >> 5;            // idx = ic*9 + ky*3 + kx
        ws[e] = wgt[o * 216 + idx];
    }
    __syncthreads();

    int p = blockIdx.x * 256 + threadIdx.x;
    int f = p >> 9, w = p & 511;
    float acc[32];
    #pragma unroll
    for (int o = 0; o < 32; o++) acc[o] = 0.f;

    for (int ic = 0; ic < 24; ic++) {
        #pragma unroll
        for (int ky = 0; ky < 3; ky++) {
            int ff = f + ky - 1;
            if ((unsigned)ff >= (unsigned)F_DIM) continue;
            const float* rp = in + (ic * F_DIM + ff) * W_DIM;
            #pragma unroll
            for (int kx = 0; kx < 3; kx++) {
                int ww = w + kx - 1;
                if ((unsigned)ww >= (unsigned)W_DIM) continue;
                float v = rp[ww];
                const float4* wp = (const float4*)&ws[(ic * 9 + ky * 3 + kx) * 32];
                #pragma unroll
                for (int o4 = 0; o4 < 8; o4++) {
                    float4 wv = wp[o4];
                    acc[o4 * 4 + 0] = fmaf(v, wv.x, acc[o4 * 4 + 0]);
                    acc[o4 * 4 + 1] = fmaf(v, wv.y, acc[o4 * 4 + 1]);
                    acc[o4 * 4 + 2] = fmaf(v, wv.z, acc[o4 * 4 + 2]);
                    acc[o4 * 4 + 3] = fmaf(v, wv.w, acc[o4 * 4 + 3]);
                }
            }
        }
    }
    #pragma unroll
    for (int o = 0; o < 32; o++) {
        float r = fmaxf(acc[o], 0.f);
        out[(o * F_DIM + f) * W_DIM + w] = r * r;
    }
}

// --------------------- 3x3 conv 32->8 + residual ---------------------------
__global__ __launch_bounds__(256)
void conv3x3_res_kernel(const float* __restrict__ in, const float* __restrict__ wgt,
                        const float* __restrict__ xin, float* __restrict__ out)
{
    __shared__ __align__(16) float ws[288 * 8];
    for (int e = threadIdx.x; e < 288 * 8; e += 256) {
        int o = e & 7, idx = e >> 3;             // idx = ic*9 + ky*3 + kx
        ws[e] = wgt[o * 288 + idx];
    }
    __syncthreads();

    int p = blockIdx.x * 256 + threadIdx.x;
    int f = p >> 9, w = p & 511;
    float acc[8] = {0.f, 0.f, 0.f, 0.f, 0.f, 0.f, 0.f, 0.f};

    for (int ic = 0; ic < 32; ic++) {
        #pragma unroll
        for (int ky = 0; ky < 3; ky++) {
            int ff = f + ky - 1;
            if ((unsigned)ff >= (unsigned)F_DIM) continue;
            const float* rp = in + (ic * F_DIM + ff) * W_DIM;
            #pragma unroll
            for (int kx = 0; kx < 3; kx++) {
                int ww = w + kx - 1;
                if ((unsigned)ww >= (unsigned)W_DIM) continue;
                float v = rp[ww];
                const float4* wp = (const float4*)&ws[(ic * 9 + ky * 3 + kx) * 8];
                float4 w0 = wp[0], w1 = wp[1];
                acc[0] = fmaf(v, w0.x, acc[0]);
                acc[1] = fmaf(v, w0.y, acc[1]);
                acc[2] = fmaf(v, w0.z, acc[2]);
                acc[3] = fmaf(v, w0.w, acc[3]);
                acc[4] = fmaf(v, w1.x, acc[4]);
                acc[5] = fmaf(v, w1.y, acc[5]);
                acc[6] = fmaf(v, w1.z, acc[6]);
                acc[7] = fmaf(v, w1.w, acc[7]);
            }
        }
    }
    #pragma unroll
    for (int o = 0; o < 8; o++) {
        int idx = (o * F_DIM + f) * W_DIM + w;
        out[idx] = xin[idx] + acc[o];
    }
}

// ------------------------------- launcher ----------------------------------
extern "C" void kernel_launch(void* const* d_in, const int* in_sizes, int n_in,
                              void* d_out, int out_size)
{
    (void)in_sizes; (void)n_in; (void)out_size;

    const float* x        = (const float*)d_in[0];
    const float* skip     = (const float*)d_in[1];
    const float* prev_qk1 = (const float*)d_in[2];
    const float* prev_qk2 = (const float*)d_in[3];
    const float* skip_qk  = (const float*)d_in[4];
    const float* g1  = (const float*)d_in[5];
    const float* b1  = (const float*)d_in[6];
    const float* wq1 = (const float*)d_in[7];
    const float* wk1 = (const float*)d_in[8];
    const float* wv1 = (const float*)d_in[9];
    const float* wo1 = (const float*)d_in[10];
    const float* g2  = (const float*)d_in[11];
    const float* b2  = (const float*)d_in[12];
    const float* wq2 = (const float*)d_in[13];
    const float* wk2 = (const float*)d_in[14];
    const float* wv2 = (const float*)d_in[15];
    const float* wo2 = (const float*)d_in[16];
    const float* g3  = (const float*)d_in[17];
    const float* b3  = (const float*)d_in[18];
    const float* wc1 = (const float*)d_in[19];
    const float* wc2 = (const float*)d_in[20];

    float* out0 = (float*)d_out;              // x + z        : 8*1024*512
    float* opq1 = out0 + 8 * FW;              // pq1          : 64*512*512
    float* opq2 = opq1 + NINST * QKSZ;        // pq2          : 64*512*512

    float *nx, *q, *k, *v, *vt, *att, *z1, *z2, *nh, *n3, *tb, *rm, *rs;
    cudaGetSymbolAddress((void**)&nx,  g_nx);
    cudaGetSymbolAddress((void**)&q,   g_q);
    cudaGetSymbolAddress((void**)&k,   g_k);
    cudaGetSymbolAddress((void**)&v,   g_v);
    cudaGetSymbolAddress((void**)&vt,  g_vt);
    cudaGetSymbolAddress((void**)&att, g_att);
    cudaGetSymbolAddress((void**)&z1,  g_z1);
    cudaGetSymbolAddress((void**)&z2,  g_z2);
    cudaGetSymbolAddress((void**)&nh,  g_nh);
    cudaGetSymbolAddress((void**)&n3,  g_n3);
    cudaGetSymbolAddress((void**)&tb,  g_t);
    cudaGetSymbolAddress((void**)&rm,  g_rm);
    cudaGetSymbolAddress((void**)&rs,  g_rs);

    // ---- block 1: LN1 + self-attention on nx -----------------------------
    ln_kernel<<<dim3(4, 8), 128>>>(x, nullptr, nullptr, g1, b1, nx);
    conv1x3_kernel<<<2048, 256>>>(nx, wq1, q, 8);
    conv1x3_kernel<<<2048, 256>>>(nx, wk1, k, 8);
    conv1x3_kernel<<<2048, 256>>>(nx, wv1, v, 8);
    vtrans_kernel<<<dim3(16, 4, NINST), dim3(32, 8)>>>(v, vt);
    qk_kernel<<<dim3(8, 8, NINST), 256>>>(q, k, prev_qk1, skip_qk, nullptr, opq1);
    rowstats_kernel<<<4096, 256>>>(opq1, rm, rs);
    av_kernel<<<dim3(8, NINST), 256>>>(opq1, rm, rs, vt, att);
    conv1x3_kernel<<<2048, 256>>>(att, wo1, z1, 8);

    // ---- block 2: LN2 on [x, z1] + cross-attention vs skip ---------------
    ln_kernel<<<dim3(4, 16), 128>>>(x, z1, nullptr, g2, b2, nh);
    conv1x3_kernel<<<2048, 256>>>(nh, wq2, q, 16);
    conv1x3_kernel<<<2048, 256>>>(skip, wk2, k, 8);
    conv1x3_kernel<<<2048, 256>>>(skip, wv2, v, 8);
    vtrans_kernel<<<dim3(16, 4, NINST), dim3(32, 8)>>>(v, vt);
    qk_kernel<<<dim3(8, 8, NINST), 256>>>(q, k, skip_qk, opq1, prev_qk2, opq2);
    rowstats_kernel<<<4096, 256>>>(opq2, rm, rs);
    av_kernel<<<dim3(8, NINST), 256>>>(opq2, rm, rs, vt, att);
    conv1x3_kernel<<<2048, 256>>>(att, wo2, z2, 8);

    // ---- block 3: LN3 on [x, z1, z2] + conv MLP + residual ---------------
    ln_kernel<<<dim3(4, 24), 128>>>(x, z1, z2, g3, b3, n3);
    conv3x3_sq_kernel<<<2048, 256>>>(n3, wc1, tb);
    conv3x3_res_kernel<<<2048, 256>>>(tb, wc2, x, out0);
}

// round 8
// speedup vs baseline: 1.1539x; 1.1539x over previous
#include <cuda_runtime.h>
#include <cuda_bf16.h>
#include <math.h>

// ---------------------------------------------------------------------------
// FrameTransformerDecoder — fp32, 8x8-microtile GEMMs (BK=16), fused QKV convs
// Shapes: B=1, C=8, OC=8, F=1024, W=512, H=8, d=128, EXP=4
// Outputs: x+z (8*1024*512), pq1 (64*512*512), pq2 (64*512*512)
// ---------------------------------------------------------------------------

#define F_DIM 1024
#define W_DIM 512
#define FW    (F_DIM * W_DIM)          // 524288
#define NINST 64                        // OC(8) * H(8)
#define QKSZ  (W_DIM * W_DIM)           // 262144 per instance
#define LOG2E 1.4426950408889634f
#define QK_SCALE 0.0883883476483184f    // 1/sqrt(128)

// ------------------------- scratch (device globals) ------------------------
__device__ float g_nx [8  * FW];
__device__ float g_q  [8  * FW];
__device__ float g_k  [8  * FW];
__device__ float g_v  [8  * FW];
__device__ float g_vt [NINST * W_DIM * 128];
__device__ float g_att[8  * FW];
__device__ float g_z1 [8  * FW];
__device__ float g_z2 [8  * FW];
__device__ float g_nh [16 * FW];
__device__ float g_n3 [24 * FW];
__device__ float g_t  [32 * FW];
__device__ float g_rm [NINST * W_DIM];
__device__ float g_rs [NINST * W_DIM];

// ------------------------------ LayerNorm ----------------------------------
__global__ __launch_bounds__(128)
void ln_kernel(const float* s0, const float* s1, const float* s2,
               const float* __restrict__ g, const float* __restrict__ b,
               float* __restrict__ out)
{
    int c = blockIdx.y;
    int w = blockIdx.x * 128 + threadIdx.x;
    const float* src = (c < 8) ? (s0 + c * FW)
                     : (c < 16) ? (s1 + (c - 8) * FW)
                                : (s2 + (c - 16) * FW);
    const float* p = src + w;
    float sum = 0.f, sq = 0.f;
    #pragma unroll 4
    for (int f = 0; f < F_DIM; f++) {
        float v = p[f * W_DIM];
        sum += v;
        sq = fmaf(v, v, sq);
    }
    float mu  = sum * (1.f / 1024.f);
    float var = sq * (1.f / 1024.f) - mu * mu;
    float inv = rsqrtf(var + 1e-8f);
    float* op = out + c * FW + w;
    const float* gp = g + c * F_DIM;
    const float* bp = b + c * F_DIM;
    #pragma unroll 4
    for (int f = 0; f < F_DIM; f++) {
        float v = p[f * W_DIM];
        op[f * W_DIM] = (v - mu) * inv * gp[f] + bp[f];
    }
}

// -------------------- 1x3 conv, NOUT projections, one input ----------------
// out_n[o,f,w] = sum_{ic,t} in[ic,f,w+t-1] * w_n[(o*IC+ic)*3+t], 8 outs each.
template<int NOUT>
__global__ __launch_bounds__(256)
void conv1x3_multi(const float* __restrict__ in,
                   const float* __restrict__ w0, const float* __restrict__ w1,
                   const float* __restrict__ w2,
                   float* __restrict__ o0, float* __restrict__ o1,
                   float* __restrict__ o2, int IC)
{
    __shared__ float ws[NOUT][8 * 16 * 3];
    int nw = 8 * IC * 3;
    for (int e = threadIdx.x; e < nw; e += 256) {
        ws[0][e] = w0[e];
        if (NOUT > 1) ws[1][e] = w1[e];
        if (NOUT > 2) ws[2][e] = w2[e];
    }
    __syncthreads();

    int p = blockIdx.x * 256 + threadIdx.x;
    int f = p >> 9, w = p & 511;
    float acc[NOUT][8];
    #pragma unroll
    for (int n = 0; n < NOUT; n++)
        #pragma unroll
        for (int o = 0; o < 8; o++) acc[n][o] = 0.f;

    for (int ic = 0; ic < IC; ic++) {
        const float* bp = in + (ic * F_DIM + f) * W_DIM + w;
        float m = bp[0];
        float l = (w > 0)   ? bp[-1] : 0.f;
        float r = (w < 511) ? bp[1]  : 0.f;
        #pragma unroll
        for (int n = 0; n < NOUT; n++) {
            #pragma unroll
            for (int o = 0; o < 8; o++) {
                const float* wp = ws[n] + (o * IC + ic) * 3;
                acc[n][o] = fmaf(l, wp[0], acc[n][o]);
                acc[n][o] = fmaf(m, wp[1], acc[n][o]);
                acc[n][o] = fmaf(r, wp[2], acc[n][o]);
            }
        }
    }
    float* outs[3] = {o0, o1, o2};
    #pragma unroll
    for (int n = 0; n < NOUT; n++)
        #pragma unroll
        for (int o = 0; o < 8; o++)
            outs[n][(o * F_DIM + f) * W_DIM + w] = acc[n][o];
}

// --------------------------- V transpose -----------------------------------
__global__ __launch_bounds__(256)
void vtrans_kernel(const float* __restrict__ v, float* __restrict__ vt)
{
    __shared__ float tile[32][33];
    int i = blockIdx.z, oc = i >> 3, h = i & 7;
    const float* vb = v + (oc * F_DIM + h * 128) * W_DIM;
    float* ob = vt + i * (W_DIM * 128);
    int w0 = blockIdx.x * 32, d0 = blockIdx.y * 32;
    int tx = threadIdx.x, ty = threadIdx.y;
    #pragma unroll
    for (int j = ty; j < 32; j += 8)
        tile[j][tx] = vb[(d0 + j) * W_DIM + w0 + tx];
    __syncthreads();
    #pragma unroll
    for (int j = ty; j < 32; j += 8)
        ob[(w0 + j) * 128 + d0 + tx] = tile[tx][j];
}

// ------------------------------ QK GEMM ------------------------------------
// 128x128 tile, BK=16, 256 threads, 8x8 microtile.
// qk[i,q,k] = scale * sum_dd Q[dd,q]*K[dd,k] + b0 (+b1) (+b2)
__global__ __launch_bounds__(256)
void qk_kernel(const float* __restrict__ q, const float* __restrict__ k,
               const float* __restrict__ b0, const float* __restrict__ b1,
               const float* __restrict__ b2, float* __restrict__ out)
{
    __shared__ __align__(16) float As[16][128];
    __shared__ __align__(16) float Bs[16][128];
    int i = blockIdx.z, oc = i >> 3, h = i & 7;
    const float* qb = q + (oc * F_DIM + h * 128) * W_DIM;
    const float* kb = k + (oc * F_DIM + h * 128) * W_DIM;
    int k0 = blockIdx.x * 128, q0 = blockIdx.y * 128;
    int t = threadIdx.x;
    int tx = t & 15, ty = t >> 4;
    int lr = t >> 4;              // load row 0..15
    int lc = (t & 15) * 4;        // load col (two float4: +0, +64)

    float acc[8][8];
    #pragma unroll
    for (int u = 0; u < 8; u++)
        #pragma unroll
        for (int v = 0; v < 8; v++) acc[u][v] = 0.f;

    for (int d0 = 0; d0 < 128; d0 += 16) {
        const float* qsrc = qb + (d0 + lr) * W_DIM + q0 + lc;
        const float* ksrc = kb + (d0 + lr) * W_DIM + k0 + lc;
        *(float4*)&As[lr][lc]      = *(const float4*)qsrc;
        *(float4*)&As[lr][lc + 64] = *(const float4*)(qsrc + 64);
        *(float4*)&Bs[lr][lc]      = *(const float4*)ksrc;
        *(float4*)&Bs[lr][lc + 64] = *(const float4*)(ksrc + 64);
        __syncthreads();
        #pragma unroll
        for (int kk = 0; kk < 16; kk++) {
            float4 a0 = *(const float4*)&As[kk][ty * 4];
            float4 a1 = *(const float4*)&As[kk][64 + ty * 4];
            float4 c0 = *(const float4*)&Bs[kk][tx * 4];
            float4 c1 = *(const float4*)&Bs[kk][64 + tx * 4];
            float av[8] = {a0.x, a0.y, a0.z, a0.w, a1.x, a1.y, a1.z, a1.w};
            float bv[8] = {c0.x, c0.y, c0.z, c0.w, c1.x, c1.y, c1.z, c1.w};
            #pragma unroll
            for (int u = 0; u < 8; u++)
                #pragma unroll
                for (int v = 0; v < 8; v++)
                    acc[u][v] = fmaf(av[u], bv[v], acc[u][v]);
        }
        __syncthreads();
    }

    int ibase = i * QKSZ;
    #pragma unroll
    for (int u = 0; u < 8; u++) {
        int qrow = q0 + ((u < 4) ? (ty * 4 + u) : (64 + ty * 4 + u - 4));
        #pragma unroll
        for (int vc = 0; vc < 2; vc++) {
            int row = ibase + qrow * W_DIM + k0 + vc * 64 + tx * 4;
            float4 o4;
            o4.x = acc[u][vc * 4 + 0] * QK_SCALE;
            o4.y = acc[u][vc * 4 + 1] * QK_SCALE;
            o4.z = acc[u][vc * 4 + 2] * QK_SCALE;
            o4.w = acc[u][vc * 4 + 3] * QK_SCALE;
            float4 t0 = *(const float4*)(b0 + row);
            o4.x += t0.x; o4.y += t0.y; o4.z += t0.z; o4.w += t0.w;
            if (b1) {
                float4 t1 = *(const float4*)(b1 + row);
                o4.x += t1.x; o4.y += t1.y; o4.z += t1.z; o4.w += t1.w;
            }
            if (b2) {
                float4 t2 = *(const float4*)(b2 + row);
                o4.x += t2.x; o4.y += t2.y; o4.z += t2.z; o4.w += t2.w;
            }
            *(float4*)(out + row) = o4;
        }
    }
}

// ---------------------------- softmax rowstats -----------------------------
__global__ __launch_bounds__(256)
void rowstats_kernel(const float* __restrict__ qk, float* __restrict__ rm,
                     float* __restrict__ rs)
{
    int row  = blockIdx.x * 8 + (threadIdx.x >> 5);
    int lane = threadIdx.x & 31;
    const float4* p = (const float4*)(qk + row * W_DIM);
    float4 vals[4];
    float mx = -1e30f;
    #pragma unroll
    for (int j = 0; j < 4; j++) {
        float4 v = p[lane + j * 32];
        vals[j] = v;
        mx = fmaxf(mx, fmaxf(fmaxf(v.x, v.y), fmaxf(v.z, v.w)));
    }
    #pragma unroll
    for (int o = 16; o > 0; o >>= 1)
        mx = fmaxf(mx, __shfl_xor_sync(0xffffffffu, mx, o));
    float s = 0.f;
    #pragma unroll
    for (int j = 0; j < 4; j++) {
        float4 v = vals[j];
        s += exp2f((v.x - mx) * LOG2E) + exp2f((v.y - mx) * LOG2E)
           + exp2f((v.z - mx) * LOG2E) + exp2f((v.w - mx) * LOG2E);
    }
    #pragma unroll
    for (int o = 16; o > 0; o >>= 1)
        s += __shfl_xor_sync(0xffffffffu, s, o);
    if (lane == 0) { rm[row] = mx; rs[row] = 1.f / s; }
}

// ------------------------------ AV GEMM ------------------------------------
// 128q x 128dd tile, BK=16, 256 threads, 8x8 microtile; exp fused on P load.
__global__ __launch_bounds__(256)
void av_kernel(const float* __restrict__ qk, const float* __restrict__ rm,
               const float* __restrict__ rs, const float* __restrict__ vt,
               float* __restrict__ att)
{
    __shared__ __align__(16) float Ps[16][128];
    __shared__ __align__(16) float Vs[16][128];
    int i = blockIdx.y, oc = i >> 3, h = i & 7;
    int q0 = blockIdx.x * 128;
    const float* qkb = qk + i * QKSZ;
    const float* vb  = vt + i * (W_DIM * 128);
    float* ab = att + (oc * F_DIM + h * 128) * W_DIM;
    int t = threadIdx.x;
    int tx = t & 15, ty = t >> 4;

    // P loader: thread handles row qq (0..127), k-chunk kp (0 or 8)
    int pq = t >> 1, kp = (t & 1) * 8;
    float m  = rm[i * W_DIM + q0 + pq];
    float si = rs[i * W_DIM + q0 + pq];
    const float* prow = qkb + (q0 + pq) * W_DIM + kp;
    // V loader
    int vr = t >> 4, vc = (t & 15) * 4;

    float acc[8][8];
    #pragma unroll
    for (int u = 0; u < 8; u++)
        #pragma unroll
        for (int v = 0; v < 8; v++) acc[u][v] = 0.f;

    for (int k0 = 0; k0 < 512; k0 += 16) {
        float4 p0 = *(const float4*)(prow + k0);
        float4 p1 = *(const float4*)(prow + k0 + 4);
        Ps[kp + 0][pq] = exp2f((p0.x - m) * LOG2E) * si;
        Ps[kp + 1][pq] = exp2f((p0.y - m) * LOG2E) * si;
        Ps[kp + 2][pq] = exp2f((p0.z - m) * LOG2E) * si;
        Ps[kp + 3][pq] = exp2f((p0.w - m) * LOG2E) * si;
        Ps[kp + 4][pq] = exp2f((p1.x - m) * LOG2E) * si;
        Ps[kp + 5][pq] = exp2f((p1.y - m) * LOG2E) * si;
        Ps[kp + 6][pq] = exp2f((p1.z - m) * LOG2E) * si;
        Ps[kp + 7][pq] = exp2f((p1.w - m) * LOG2E) * si;
        const float* vsrc = vb + (k0 + vr) * 128 + vc;
        *(float4*)&Vs[vr][vc]      = *(const float4*)vsrc;
        *(float4*)&Vs[vr][vc + 64] = *(const float4*)(vsrc + 64);
        __syncthreads();
        #pragma unroll
        for (int kk = 0; kk < 16; kk++) {
            float4 a0 = *(const float4*)&Ps[kk][ty * 4];
            float4 a1 = *(const float4*)&Ps[kk][64 + ty * 4];
            float4 c0 = *(const float4*)&Vs[kk][tx * 4];
            float4 c1 = *(const float4*)&Vs[kk][64 + tx * 4];
            float av[8] = {a0.x, a0.y, a0.z, a0.w, a1.x, a1.y, a1.z, a1.w};
            float bv[8] = {c0.x, c0.y, c0.z, c0.w, c1.x, c1.y, c1.z, c1.w};
            #pragma unroll
            for (int u = 0; u < 8; u++)
                #pragma unroll
                for (int v = 0; v < 8; v++)
                    acc[u][v] = fmaf(av[u], bv[v], acc[u][v]);
        }
        __syncthreads();
    }

    // store: att[dd, q], dd = {tx*4+j, 64+tx*4+j}, q chunks {ty*4, 64+ty*4}
    #pragma unroll
    for (int vc2 = 0; vc2 < 2; vc2++) {
        #pragma unroll
        for (int j = 0; j < 4; j++) {
            int dd = vc2 * 64 + tx * 4 + j;
            float* op = ab + dd * W_DIM + q0;
            *(float4*)&op[ty * 4] = make_float4(
                acc[0][vc2 * 4 + j], acc[1][vc2 * 4 + j],
                acc[2][vc2 * 4 + j], acc[3][vc2 * 4 + j]);
            *(float4*)&op[64 + ty * 4] = make_float4(
                acc[4][vc2 * 4 + j], acc[5][vc2 * 4 + j],
                acc[6][vc2 * 4 + j], acc[7][vc2 * 4 + j]);
        }
    }
}

// --------------------- 3x3 conv 24->32 + SquaredReLU -----------------------
__global__ __launch_bounds__(256)
void conv3x3_sq_kernel(const float* __restrict__ in, const float* __restrict__ wgt,
                       float* __restrict__ out)
{
    __shared__ __align__(16) float ws[216 * 32];
    for (int e = threadIdx.x; e < 216 * 32; e += 256) {
        int o = e & 31, idx = e >> 5;            // idx = ic*9 + ky*3 + kx
        ws[e] = wgt[o * 216 + idx];
    }
    __syncthreads();

    int p = blockIdx.x * 256 + threadIdx.x;
    int f = p >> 9, w = p & 511;
    float acc[32];
    #pragma unroll
    for (int o = 0; o < 32; o++) acc[o] = 0.f;

    for (int ic = 0; ic < 24; ic++) {
        #pragma unroll
        for (int ky = 0; ky < 3; ky++) {
            int ff = f + ky - 1;
            if ((unsigned)ff >= (unsigned)F_DIM) continue;
            const float* rp = in + (ic * F_DIM + ff) * W_DIM;
            #pragma unroll
            for (int kx = 0; kx < 3; kx++) {
                int ww = w + kx - 1;
                if ((unsigned)ww >= (unsigned)W_DIM) continue;
                float v = rp[ww];
                const float4* wp = (const float4*)&ws[(ic * 9 + ky * 3 + kx) * 32];
                #pragma unroll
                for (int o4 = 0; o4 < 8; o4++) {
                    float4 wv = wp[o4];
                    acc[o4 * 4 + 0] = fmaf(v, wv.x, acc[o4 * 4 + 0]);
                    acc[o4 * 4 + 1] = fmaf(v, wv.y, acc[o4 * 4 + 1]);
                    acc[o4 * 4 + 2] = fmaf(v, wv.z, acc[o4 * 4 + 2]);
                    acc[o4 * 4 + 3] = fmaf(v, wv.w, acc[o4 * 4 + 3]);
                }
            }
        }
    }
    #pragma unroll
    for (int o = 0; o < 32; o++) {
        float r = fmaxf(acc[o], 0.f);
        out[(o * F_DIM + f) * W_DIM + w] = r * r;
    }
}

// --------------------- 3x3 conv 32->8 + residual ---------------------------
__global__ __launch_bounds__(256)
void conv3x3_res_kernel(const float* __restrict__ in, const float* __restrict__ wgt,
                        const float* __restrict__ xin, float* __restrict__ out)
{
    __shared__ __align__(16) float ws[288 * 8];
    for (int e = threadIdx.x; e < 288 * 8; e += 256) {
        int o = e & 7, idx = e >> 3;             // idx = ic*9 + ky*3 + kx
        ws[e] = wgt[o * 288 + idx];
    }
    __syncthreads();

    int p = blockIdx.x * 256 + threadIdx.x;
    int f = p >> 9, w = p & 511;
    float acc[8] = {0.f, 0.f, 0.f, 0.f, 0.f, 0.f, 0.f, 0.f};

    for (int ic = 0; ic < 32; ic++) {
        #pragma unroll
        for (int ky = 0; ky < 3; ky++) {
            int ff = f + ky - 1;
            if ((unsigned)ff >= (unsigned)F_DIM) continue;
            const float* rp = in + (ic * F_DIM + ff) * W_DIM;
            #pragma unroll
            for (int kx = 0; kx < 3; kx++) {
                int ww = w + kx - 1;
                if ((unsigned)ww >= (unsigned)W_DIM) continue;
                float v = rp[ww];
                const float4* wp = (const float4*)&ws[(ic * 9 + ky * 3 + kx) * 8];
                float4 w0 = wp[0], w1 = wp[1];
                acc[0] = fmaf(v, w0.x, acc[0]);
                acc[1] = fmaf(v, w0.y, acc[1]);
                acc[2] = fmaf(v, w0.z, acc[2]);
                acc[3] = fmaf(v, w0.w, acc[3]);
                acc[4] = fmaf(v, w1.x, acc[4]);
                acc[5] = fmaf(v, w1.y, acc[5]);
                acc[6] = fmaf(v, w1.z, acc[6]);
                acc[7] = fmaf(v, w1.w, acc[7]);
            }
        }
    }
    #pragma unroll
    for (int o = 0; o < 8; o++) {
        int idx = (o * F_DIM + f) * W_DIM + w;
        out[idx] = xin[idx] + acc[o];
    }
}

// ------------------------------- launcher ----------------------------------
extern "C" void kernel_launch(void* const* d_in, const int* in_sizes, int n_in,
                              void* d_out, int out_size)
{
    (void)in_sizes; (void)n_in; (void)out_size;

    const float* x        = (const float*)d_in[0];
    const float* skip     = (const float*)d_in[1];
    const float* prev_qk1 = (const float*)d_in[2];
    const float* prev_qk2 = (const float*)d_in[3];
    const float* skip_qk  = (const float*)d_in[4];
    const float* g1  = (const float*)d_in[5];
    const float* b1  = (const float*)d_in[6];
    const float* wq1 = (const float*)d_in[7];
    const float* wk1 = (const float*)d_in[8];
    const float* wv1 = (const float*)d_in[9];
    const float* wo1 = (const float*)d_in[10];
    const float* g2  = (const float*)d_in[11];
    const float* b2  = (const float*)d_in[12];
    const float* wq2 = (const float*)d_in[13];
    const float* wk2 = (const float*)d_in[14];
    const float* wv2 = (const float*)d_in[15];
    const float* wo2 = (const float*)d_in[16];
    const float* g3  = (const float*)d_in[17];
    const float* b3  = (const float*)d_in[18];
    const float* wc1 = (const float*)d_in[19];
    const float* wc2 = (const float*)d_in[20];

    float* out0 = (float*)d_out;              // x + z        : 8*1024*512
    float* opq1 = out0 + 8 * FW;              // pq1          : 64*512*512
    float* opq2 = opq1 + NINST * QKSZ;        // pq2          : 64*512*512

    float *nx, *q, *k, *v, *vt, *att, *z1, *z2, *nh, *n3, *tb, *rm, *rs;
    cudaGetSymbolAddress((void**)&nx,  g_nx);
    cudaGetSymbolAddress((void**)&q,   g_q);
    cudaGetSymbolAddress((void**)&k,   g_k);
    cudaGetSymbolAddress((void**)&v,   g_v);
    cudaGetSymbolAddress((void**)&vt,  g_vt);
    cudaGetSymbolAddress((void**)&att, g_att);
    cudaGetSymbolAddress((void**)&z1,  g_z1);
    cudaGetSymbolAddress((void**)&z2,  g_z2);
    cudaGetSymbolAddress((void**)&nh,  g_nh);
    cudaGetSymbolAddress((void**)&n3,  g_n3);
    cudaGetSymbolAddress((void**)&tb,  g_t);
    cudaGetSymbolAddress((void**)&rm,  g_rm);
    cudaGetSymbolAddress((void**)&rs,  g_rs);

    // ---- block 1: LN1 + self-attention on nx -----------------------------
    ln_kernel<<<dim3(4, 8), 128>>>(x, nullptr, nullptr, g1, b1, nx);
    conv1x3_multi<3><<<2048, 256>>>(nx, wq1, wk1, wv1, q, k, v, 8);
    vtrans_kernel<<<dim3(16, 4, NINST), dim3(32, 8)>>>(v, vt);
    qk_kernel<<<dim3(4, 4, NINST), 256>>>(q, k, prev_qk1, skip_qk, nullptr, opq1);
    rowstats_kernel<<<4096, 256>>>(opq1, rm, rs);
    av_kernel<<<dim3(4, NINST), 256>>>(opq1, rm, rs, vt, att);
    conv1x3_multi<1><<<2048, 256>>>(att, wo1, nullptr, nullptr, z1, nullptr, nullptr, 8);

    // ---- block 2: LN2 on [x, z1] + cross-attention vs skip ---------------
    ln_kernel<<<dim3(4, 16), 128>>>(x, z1, nullptr, g2, b2, nh);
    conv1x3_multi<1><<<2048, 256>>>(nh, wq2, nullptr, nullptr, q, nullptr, nullptr, 16);
    conv1x3_multi<2><<<2048, 256>>>(skip, wk2, wv2, nullptr, k, v, nullptr, 8);
    vtrans_kernel<<<dim3(16, 4, NINST), dim3(32, 8)>>>(v, vt);
    qk_kernel<<<dim3(4, 4, NINST), 256>>>(q, k, skip_qk, opq1, prev_qk2, opq2);
    rowstats_kernel<<<4096, 256>>>(opq2, rm, rs);
    av_kernel<<<dim3(4, NINST), 256>>>(opq2, rm, rs, vt, att);
    conv1x3_multi<1><<<2048, 256>>>(att, wo2, nullptr, nullptr, z2, nullptr, nullptr, 8);

    // ---- block 3: LN3 on [x, z1, z2] + conv MLP + residual ---------------
    ln_kernel<<<dim3(4, 24), 128>>>(x, z1, z2, g3, b3, n3);
    conv3x3_sq_kernel<<<2048, 256>>>(n3, wc1, tb);
    conv3x3_res_kernel<<<2048, 256>>>(tb, wc2, x, out0);
}

// round 12
// speedup vs baseline: 1.1733x; 1.0168x over previous
#include <cuda_runtime.h>
#include <cuda_bf16.h>
#include <math.h>
#include <stdint.h>

// ---------------------------------------------------------------------------
// FrameTransformerDecoder — qk & av via split-bf16 mma.sync (HMMA fallback,
// compiles for plain sm_103 target); convs/LN fp32 SIMT.
// Shapes: B=1, C=8, OC=8, F=1024, W=512, H=8, d=128, EXP=4
// ---------------------------------------------------------------------------

#define F_DIM 1024
#define W_DIM 512
#define FW    (F_DIM * W_DIM)
#define NINST 64
#define QKSZ  (W_DIM * W_DIM)
#define LOG2E 1.4426950408889634f
#define QK_SCALE 0.0883883476483184f

// ------------------------- scratch (device globals) ------------------------
__device__ float g_nx [8  * FW];
__device__ float g_q  [8  * FW];
__device__ float g_k  [8  * FW];
__device__ float g_v  [8  * FW];
__device__ float g_att[8  * FW];
__device__ float g_z1 [8  * FW];
__device__ float g_z2 [8  * FW];
__device__ float g_nh [16 * FW];
__device__ float g_n3 [24 * FW];
__device__ float g_t  [32 * FW];
__device__ float g_rm [NINST * W_DIM];
__device__ float g_rs [NINST * W_DIM];
// split-bf16 transposed q/k: [inst][w(512)][dd(128)]
__device__ __nv_bfloat16 g_qth[NINST * W_DIM * 128];
__device__ __nv_bfloat16 g_qtl[NINST * W_DIM * 128];
__device__ __nv_bfloat16 g_kth[NINST * W_DIM * 128];
__device__ __nv_bfloat16 g_ktl[NINST * W_DIM * 128];
// split-bf16 v in natural layout [inst*128+dd][w]
__device__ __nv_bfloat16 g_vh [8 * FW];
__device__ __nv_bfloat16 g_vl [8 * FW];

// ------------------------------ PTX helpers --------------------------------
__device__ __forceinline__ uint32_t smem_u32(const void* p) {
    uint32_t a;
    asm("{ .reg .u64 tmp; cvta.to.shared.u64 tmp, %1; cvt.u32.u64 %0, tmp; }"
        : "=r"(a) : "l"(p));
    return a;
}
__device__ __forceinline__ void ldsm4(uint32_t* r, uint32_t addr) {
    asm volatile("ldmatrix.sync.aligned.m8n8.x4.shared.b16 {%0,%1,%2,%3}, [%4];"
        : "=r"(r[0]), "=r"(r[1]), "=r"(r[2]), "=r"(r[3]) : "r"(addr));
}
__device__ __forceinline__ void mma16816(float* d, const uint32_t* a, const uint32_t* b) {
    asm volatile(
        "mma.sync.aligned.m16n8k16.row.col.f32.bf16.bf16.f32 "
        "{%0,%1,%2,%3}, {%4,%5,%6,%7}, {%8,%9}, {%0,%1,%2,%3};"
        : "+f"(d[0]), "+f"(d[1]), "+f"(d[2]), "+f"(d[3])
        : "r"(a[0]), "r"(a[1]), "r"(a[2]), "r"(a[3]), "r"(b[0]), "r"(b[1]));
}

// ------------------------------ LayerNorm ----------------------------------
__global__ __launch_bounds__(128)
void ln_kernel(const float* s0, const float* s1, const float* s2,
               const float* __restrict__ g, const float* __restrict__ b,
               float* __restrict__ out)
{
    int c = blockIdx.y;
    int w = blockIdx.x * 128 + threadIdx.x;
    const float* src = (c < 8) ? (s0 + c * FW)
                     : (c < 16) ? (s1 + (c - 8) * FW)
                                : (s2 + (c - 16) * FW);
    const float* p = src + w;
    float sum = 0.f, sq = 0.f;
    #pragma unroll 4
    for (int f = 0; f < F_DIM; f++) {
        float v = p[f * W_DIM];
        sum += v;
        sq = fmaf(v, v, sq);
    }
    float mu  = sum * (1.f / 1024.f);
    float var = sq * (1.f / 1024.f) - mu * mu;
    float inv = rsqrtf(var + 1e-8f);
    float* op = out + c * FW + w;
    const float* gp = g + c * F_DIM;
    const float* bp = b + c * F_DIM;
    #pragma unroll 4
    for (int f = 0; f < F_DIM; f++) {
        float v = p[f * W_DIM];
        op[f * W_DIM] = (v - mu) * inv * gp[f] + bp[f];
    }
}

// -------------------- 1x3 conv, NOUT projections ---------------------------
template<int NOUT>
__global__ __launch_bounds__(256)
void conv1x3_multi(const float* __restrict__ in,
                   const float* __restrict__ w0, const float* __restrict__ w1,
                   const float* __restrict__ w2,
                   float* __restrict__ o0, float* __restrict__ o1,
                   float* __restrict__ o2, int IC)
{
    __shared__ float ws[NOUT][8 * 16 * 3];
    int nw = 8 * IC * 3;
    for (int e = threadIdx.x; e < nw; e += 256) {
        ws[0][e] = w0[e];
        if (NOUT > 1) ws[1][e] = w1[e];
        if (NOUT > 2) ws[2][e] = w2[e];
    }
    __syncthreads();

    int p = blockIdx.x * 256 + threadIdx.x;
    int f = p >> 9, w = p & 511;
    float acc[NOUT][8];
    #pragma unroll
    for (int n = 0; n < NOUT; n++)
        #pragma unroll
        for (int o = 0; o < 8; o++) acc[n][o] = 0.f;

    for (int ic = 0; ic < IC; ic++) {
        const float* bp = in + (ic * F_DIM + f) * W_DIM + w;
        float m = bp[0];
        float l = (w > 0)   ? bp[-1] : 0.f;
        float r = (w < 511) ? bp[1]  : 0.f;
        #pragma unroll
        for (int n = 0; n < NOUT; n++) {
            #pragma unroll
            for (int o = 0; o < 8; o++) {
                const float* wp = ws[n] + (o * IC + ic) * 3;
                acc[n][o] = fmaf(l, wp[0], acc[n][o]);
                acc[n][o] = fmaf(m, wp[1], acc[n][o]);
                acc[n][o] = fmaf(r, wp[2], acc[n][o]);
            }
        }
    }
    float* outs[3] = {o0, o1, o2};
    #pragma unroll
    for (int n = 0; n < NOUT; n++)
        #pragma unroll
        for (int o = 0; o < 8; o++)
            outs[n][(o * F_DIM + f) * W_DIM + w] = acc[n][o];
}

// ---------------- transpose + split fp32 -> bf16 hi/lo ---------------------
// in[(i*128+dd)][w] fp32  ->  oh/ol[i][w][dd] bf16
__global__ __launch_bounds__(256)
void split_trans_kernel(const float* __restrict__ in,
                        __nv_bfloat16* __restrict__ oh,
                        __nv_bfloat16* __restrict__ ol)
{
    __shared__ float tile[32][33];
    int i = blockIdx.z;
    int w0 = blockIdx.x * 32, d0 = blockIdx.y * 32;
    int tx = threadIdx.x, ty = threadIdx.y;
    const float* ib = in + ((size_t)i * 128 + d0) * W_DIM + w0;
    #pragma unroll
    for (int j = ty; j < 32; j += 8)
        tile[j][tx] = ib[j * W_DIM + tx];
    __syncthreads();
    size_t ob = (size_t)i * (W_DIM * 128) + (size_t)w0 * 128 + d0;
    #pragma unroll
    for (int j = ty; j < 32; j += 8) {
        float x = tile[tx][j];
        __nv_bfloat16 h = __float2bfloat16(x);
        float hf = __bfloat162float(h);
        __nv_bfloat16 l = __float2bfloat16(x - hf);
        oh[ob + (size_t)j * 128 + tx] = h;
        ol[ob + (size_t)j * 128 + tx] = l;
    }
}

// --------------------- elementwise split fp32 -> bf16 hi/lo ----------------
__global__ __launch_bounds__(256)
void split_v_kernel(const float* __restrict__ v,
                    __nv_bfloat16* __restrict__ vh,
                    __nv_bfloat16* __restrict__ vl)
{
    size_t idx = ((size_t)blockIdx.x * 256 + threadIdx.x) * 4;
    float4 x = *(const float4*)(v + idx);
    __nv_bfloat16 h[4], l[4];
    float xs[4] = {x.x, x.y, x.z, x.w};
    #pragma unroll
    for (int j = 0; j < 4; j++) {
        h[j] = __float2bfloat16(xs[j]);
        l[j] = __float2bfloat16(xs[j] - __bfloat162float(h[j]));
    }
    *(uint2*)(vh + idx) = *(uint2*)h;
    *(uint2*)(vl + idx) = *(uint2*)l;
}

// ------------------------- QK GEMM via mma.sync ----------------------------
// out[i,q,k] = SCALE * sum_d Q[q,d]*K[k,d] + b0 + b1 (+ b2)
// A = Qh/Ql [w][d], B = Kh/Kl [w][d] (both d-contiguous -> row.col mma).
// CTA 128q x 128k, 8 warps (2m x 4n), warp 64x32, K staged in 32-d chunks.
__global__ __launch_bounds__(256)
void qk_mma_kernel(const __nv_bfloat16* __restrict__ qh, const __nv_bfloat16* __restrict__ ql,
                   const __nv_bfloat16* __restrict__ kh, const __nv_bfloat16* __restrict__ kl,
                   const float* __restrict__ b0, const float* __restrict__ b1,
                   const float* __restrict__ b2, float* __restrict__ out)
{
    __shared__ __align__(16) __nv_bfloat16 sQh[128][40];
    __shared__ __align__(16) __nv_bfloat16 sQl[128][40];
    __shared__ __align__(16) __nv_bfloat16 sKh[128][40];
    __shared__ __align__(16) __nv_bfloat16 sKl[128][40];

    int i = blockIdx.z, k0 = blockIdx.x << 7, q0 = blockIdx.y << 7;
    int t = threadIdx.x, wid = t >> 5, lane = t & 31;
    int wm = (wid >> 2) * 64, wn = (wid & 3) * 32;

    const __nv_bfloat16* qhg = qh + ((size_t)i * W_DIM + q0) * 128;
    const __nv_bfloat16* qlg = ql + ((size_t)i * W_DIM + q0) * 128;
    const __nv_bfloat16* khg = kh + ((size_t)i * W_DIM + k0) * 128;
    const __nv_bfloat16* klg = kl + ((size_t)i * W_DIM + k0) * 128;

    float acc[4][4][4];
    #pragma unroll
    for (int m = 0; m < 4; m++)
        #pragma unroll
        for (int n = 0; n < 4; n++)
            #pragma unroll
            for (int r = 0; r < 4; r++) acc[m][n][r] = 0.f;

    for (int d0 = 0; d0 < 128; d0 += 32) {
        {
            int row = t & 127;
            const uint4* g0; const uint4* g1; uint4* s0; uint4* s1;
            if (t < 128) {
                g0 = (const uint4*)(qhg + (size_t)row * 128 + d0);
                g1 = (const uint4*)(qlg + (size_t)row * 128 + d0);
                s0 = (uint4*)&sQh[row][0];
                s1 = (uint4*)&sQl[row][0];
            } else {
                g0 = (const uint4*)(khg + (size_t)row * 128 + d0);
                g1 = (const uint4*)(klg + (size_t)row * 128 + d0);
                s0 = (uint4*)&sKh[row][0];
                s1 = (uint4*)&sKl[row][0];
            }
            #pragma unroll
            for (int c2 = 0; c2 < 4; c2++) { s0[c2] = g0[c2]; s1[c2] = g1[c2]; }
        }
        __syncthreads();
        #pragma unroll
        for (int kk = 0; kk < 32; kk += 16) {
            int arow = lane & 15;
            int ac = kk + (lane >> 4) * 8;
            uint32_t bh[8], bl[8];
            ldsm4(bh,     smem_u32(&sKh[wn + arow][ac]));
            ldsm4(bh + 4, smem_u32(&sKh[wn + 16 + arow][ac]));
            ldsm4(bl,     smem_u32(&sKl[wn + arow][ac]));
            ldsm4(bl + 4, smem_u32(&sKl[wn + 16 + arow][ac]));
            #pragma unroll
            for (int m = 0; m < 4; m++) {
                uint32_t ah[4], al[4];
                ldsm4(ah, smem_u32(&sQh[wm + m * 16 + arow][ac]));
                ldsm4(al, smem_u32(&sQl[wm + m * 16 + arow][ac]));
                #pragma unroll
                for (int n = 0; n < 4; n++) {
                    int bi = (n >> 1) * 4 + (n & 1);
                    uint32_t fh[2] = {bh[bi], bh[bi + 2]};
                    uint32_t fl[2] = {bl[bi], bl[bi + 2]};
                    mma16816(acc[m][n], ah, fh);
                    mma16816(acc[m][n], ah, fl);
                    mma16816(acc[m][n], al, fh);
                }
            }
        }
        __syncthreads();
    }

    int g = lane >> 2, c = lane & 3;
    #pragma unroll
    for (int m = 0; m < 4; m++) {
        #pragma unroll
        for (int n = 0; n < 4; n++) {
            int col = k0 + wn + n * 8 + c * 2;
            #pragma unroll
            for (int h2 = 0; h2 < 2; h2++) {
                int row = q0 + wm + m * 16 + g + h2 * 8;
                size_t idx = (size_t)i * QKSZ + (size_t)row * W_DIM + col;
                float vx = acc[m][n][h2 * 2 + 0] * QK_SCALE + b0[idx] + b1[idx];
                float vy = acc[m][n][h2 * 2 + 1] * QK_SCALE + b0[idx + 1] + b1[idx + 1];
                if (b2) { vx += b2[idx]; vy += b2[idx + 1]; }
                *(float2*)(out + idx) = make_float2(vx, vy);
            }
        }
    }
}

// ---------------------------- softmax rowstats -----------------------------
__global__ __launch_bounds__(256)
void rowstats_kernel(const float* __restrict__ qk, float* __restrict__ rm,
                     float* __restrict__ rs)
{
    int row  = blockIdx.x * 8 + (threadIdx.x >> 5);
    int lane = threadIdx.x & 31;
    const float4* p = (const float4*)(qk + (size_t)row * W_DIM);
    float4 vals[4];
    float mx = -1e30f;
    #pragma unroll
    for (int j = 0; j < 4; j++) {
        float4 v = p[lane + j * 32];
        vals[j] = v;
        mx = fmaxf(mx, fmaxf(fmaxf(v.x, v.y), fmaxf(v.z, v.w)));
    }
    #pragma unroll
    for (int o = 16; o > 0; o >>= 1)
        mx = fmaxf(mx, __shfl_xor_sync(0xffffffffu, mx, o));
    float s = 0.f;
    #pragma unroll
    for (int j = 0; j < 4; j++) {
        float4 v = vals[j];
        s += exp2f((v.x - mx) * LOG2E) + exp2f((v.y - mx) * LOG2E)
           + exp2f((v.z - mx) * LOG2E) + exp2f((v.w - mx) * LOG2E);
    }
    #pragma unroll
    for (int o = 16; o > 0; o >>= 1)
        s += __shfl_xor_sync(0xffffffffu, s, o);
    if (lane == 0) { rm[row] = mx; rs[row] = 1.f / s; }
}

// ------------------------- AV GEMM via mma.sync ----------------------------
// att[i*128+dd][q] = sum_k softmax(qk)[q,k] * V[dd,k]
// A = P (exp computed + split in-kernel), B = Vh/Vl natural [dd][w].
// CTA 128q x 128dd, 8 warps (2m x 4n), k staged in 32-wide chunks.
__global__ __launch_bounds__(256)
void av_mma_kernel(const float* __restrict__ qk, const float* __restrict__ rm,
                   const float* __restrict__ rs,
                   const __nv_bfloat16* __restrict__ vh,
                   const __nv_bfloat16* __restrict__ vl,
                   float* __restrict__ att)
{
    __shared__ __align__(16) __nv_bfloat16 sPh[128][40];
    __shared__ __align__(16) __nv_bfloat16 sPl[128][40];
    __shared__ __align__(16) __nv_bfloat16 sVh[128][40];
    __shared__ __align__(16) __nv_bfloat16 sVl[128][40];

    int i = blockIdx.y, q0 = blockIdx.x << 7;
    int t = threadIdx.x, wid = t >> 5, lane = t & 31;
    int wm = (wid >> 2) * 64, wn = (wid & 3) * 32;

    const float* qkb = qk + (size_t)i * QKSZ;
    const __nv_bfloat16* vhb = vh + (size_t)i * 128 * W_DIM;
    const __nv_bfloat16* vlb = vl + (size_t)i * 128 * W_DIM;
    float* attb = att + (size_t)i * 128 * W_DIM;

    int prow = t >> 1, pch = (t & 1) * 16;
    float mrow = rm[i * W_DIM + q0 + prow];
    float srow = rs[i * W_DIM + q0 + prow];
    const float4* prows = (const float4*)(qkb + (size_t)(q0 + prow) * W_DIM + pch);

    float acc[4][4][4];
    #pragma unroll
    for (int m = 0; m < 4; m++)
        #pragma unroll
        for (int n = 0; n < 4; n++)
            #pragma unroll
            for (int r = 0; r < 4; r++) acc[m][n][r] = 0.f;

    for (int k0c = 0; k0c < 512; k0c += 32) {
        {
            union { uint4 u[2]; __nv_bfloat16 h[16]; } H, L;
            #pragma unroll
            for (int j = 0; j < 4; j++) {
                float4 p4 = prows[(k0c >> 2) + j];
                float e[4];
                e[0] = exp2f((p4.x - mrow) * LOG2E) * srow;
                e[1] = exp2f((p4.y - mrow) * LOG2E) * srow;
                e[2] = exp2f((p4.z - mrow) * LOG2E) * srow;
                e[3] = exp2f((p4.w - mrow) * LOG2E) * srow;
                #pragma unroll
                for (int x2 = 0; x2 < 4; x2++) {
                    __nv_bfloat16 hh = __float2bfloat16(e[x2]);
                    H.h[j * 4 + x2] = hh;
                    L.h[j * 4 + x2] = __float2bfloat16(e[x2] - __bfloat162float(hh));
                }
            }
            *(uint4*)&sPh[prow][pch]     = H.u[0];
            *(uint4*)&sPh[prow][pch + 8] = H.u[1];
            *(uint4*)&sPl[prow][pch]     = L.u[0];
            *(uint4*)&sPl[prow][pch + 8] = L.u[1];
            if (t < 128) {
                const uint4* gv0 = (const uint4*)(vhb + (size_t)t * W_DIM + k0c);
                const uint4* gv1 = (const uint4*)(vlb + (size_t)t * W_DIM + k0c);
                uint4* s0 = (uint4*)&sVh[t][0];
                uint4* s1 = (uint4*)&sVl[t][0];
                #pragma unroll
                for (int c2 = 0; c2 < 4; c2++) { s0[c2] = gv0[c2]; s1[c2] = gv1[c2]; }
            }
        }
        __syncthreads();
        #pragma unroll
        for (int kk = 0; kk < 32; kk += 16) {
            int arow = lane & 15;
            int ac = kk + (lane >> 4) * 8;
            uint32_t bh[8], bl[8];
            ldsm4(bh,     smem_u32(&sVh[wn + arow][ac]));
            ldsm4(bh + 4, smem_u32(&sVh[wn + 16 + arow][ac]));
            ldsm4(bl,     smem_u32(&sVl[wn + arow][ac]));
            ldsm4(bl + 4, smem_u32(&sVl[wn + 16 + arow][ac]));
            #pragma unroll
            for (int m = 0; m < 4; m++) {
                uint32_t ah[4], al[4];
                ldsm4(ah, smem_u32(&sPh[wm + m * 16 + arow][ac]));
                ldsm4(al, smem_u32(&sPl[wm + m * 16 + arow][ac]));
                #pragma unroll
                for (int n = 0; n < 4; n++) {
                    int bi = (n >> 1) * 4 + (n & 1);
                    uint32_t fh[2] = {bh[bi], bh[bi + 2]};
                    uint32_t fl[2] = {bl[bi], bl[bi + 2]};
                    mma16816(acc[m][n], ah, fh);
                    mma16816(acc[m][n], ah, fl);
                    mma16816(acc[m][n], al, fh);
                }
            }
        }
        __syncthreads();
    }

    int g = lane >> 2, c = lane & 3;
    #pragma unroll
    for (int m = 0; m < 4; m++) {
        #pragma unroll
        for (int n = 0; n < 4; n++) {
            int dd = wn + n * 8 + c * 2;
            #pragma unroll
            for (int h2 = 0; h2 < 2; h2++) {
                int row = q0 + wm + m * 16 + g + h2 * 8;
                attb[(size_t)dd * W_DIM + row]       = acc[m][n][h2 * 2 + 0];
                attb[(size_t)(dd + 1) * W_DIM + row] = acc[m][n][h2 * 2 + 1];
            }
        }
    }
}

// --------------------- 3x3 conv 24->32 + SquaredReLU -----------------------
__global__ __launch_bounds__(256)
void conv3x3_sq_kernel(const float* __restrict__ in, const float* __restrict__ wgt,
                       float* __restrict__ out)
{
    __shared__ __align__(16) float ws[216 * 32];
    for (int e = threadIdx.x; e < 216 * 32; e += 256) {
        int o = e & 31, idx = e >> 5;
        ws[e] = wgt[o * 216 + idx];
    }
    __syncthreads();

    int p = blockIdx.x * 256 + threadIdx.x;
    int f = p >> 9, w = p & 511;
    float acc[32];
    #pragma unroll
    for (int o = 0; o < 32; o++) acc[o] = 0.f;

    for (int ic = 0; ic < 24; ic++) {
        #pragma unroll
        for (int ky = 0; ky < 3; ky++) {
            int ff = f + ky - 1;
            if ((unsigned)ff >= (unsigned)F_DIM) continue;
            const float* rp = in + (ic * F_DIM + ff) * W_DIM;
            #pragma unroll
            for (int kx = 0; kx < 3; kx++) {
                int ww = w + kx - 1;
                if ((unsigned)ww >= (unsigned)W_DIM) continue;
                float v = rp[ww];
                const float4* wp = (const float4*)&ws[(ic * 9 + ky * 3 + kx) * 32];
                #pragma unroll
                for (int o4 = 0; o4 < 8; o4++) {
                    float4 wv = wp[o4];
                    acc[o4 * 4 + 0] = fmaf(v, wv.x, acc[o4 * 4 + 0]);
                    acc[o4 * 4 + 1] = fmaf(v, wv.y, acc[o4 * 4 + 1]);
                    acc[o4 * 4 + 2] = fmaf(v, wv.z, acc[o4 * 4 + 2]);
                    acc[o4 * 4 + 3] = fmaf(v, wv.w, acc[o4 * 4 + 3]);
                }
            }
        }
    }
    #pragma unroll
    for (int o = 0; o < 32; o++) {
        float r = fmaxf(acc[o], 0.f);
        out[(o * F_DIM + f) * W_DIM + w] = r * r;
    }
}

// --------------------- 3x3 conv 32->8 + residual ---------------------------
__global__ __launch_bounds__(256)
void conv3x3_res_kernel(const float* __restrict__ in, const float* __restrict__ wgt,
                        const float* __restrict__ xin, float* __restrict__ out)
{
    __shared__ __align__(16) float ws[288 * 8];
    for (int e = threadIdx.x; e < 288 * 8; e += 256) {
        int o = e & 7, idx = e >> 3;
        ws[e] = wgt[o * 288 + idx];
    }
    __syncthreads();

    int p = blockIdx.x * 256 + threadIdx.x;
    int f = p >> 9, w = p & 511;
    float acc[8] = {0.f, 0.f, 0.f, 0.f, 0.f, 0.f, 0.f, 0.f};

    for (int ic = 0; ic < 32; ic++) {
        #pragma unroll
        for (int ky = 0; ky < 3; ky++) {
            int ff = f + ky - 1;
            if ((unsigned)ff >= (unsigned)F_DIM) continue;
            const float* rp = in + (ic * F_DIM + ff) * W_DIM;
            #pragma unroll
            for (int kx = 0; kx < 3; kx++) {
                int ww = w + kx - 1;
                if ((unsigned)ww >= (unsigned)W_DIM) continue;
                float v = rp[ww];
                const float4* wp = (const float4*)&ws[(ic * 9 + ky * 3 + kx) * 8];
                float4 w0 = wp[0], w1 = wp[1];
                acc[0] = fmaf(v, w0.x, acc[0]);
                acc[1] = fmaf(v, w0.y, acc[1]);
                acc[2] = fmaf(v, w0.z, acc[2]);
                acc[3] = fmaf(v, w0.w, acc[3]);
                acc[4] = fmaf(v, w1.x, acc[4]);
                acc[5] = fmaf(v, w1.y, acc[5]);
                acc[6] = fmaf(v, w1.z, acc[6]);
                acc[7] = fmaf(v, w1.w, acc[7]);
            }
        }
    }
    #pragma unroll
    for (int o = 0; o < 8; o++) {
        int idx = (o * F_DIM + f) * W_DIM + w;
        out[idx] = xin[idx] + acc[o];
    }
}

// ------------------------------- launcher ----------------------------------
extern "C" void kernel_launch(void* const* d_in, const int* in_sizes, int n_in,
                              void* d_out, int out_size)
{
    (void)in_sizes; (void)n_in; (void)out_size;

    const float* x        = (const float*)d_in[0];
    const float* skip     = (const float*)d_in[1];
    const float* prev_qk1 = (const float*)d_in[2];
    const float* prev_qk2 = (const float*)d_in[3];
    const float* skip_qk  = (const float*)d_in[4];
    const float* g1  = (const float*)d_in[5];
    const float* b1  = (const float*)d_in[6];
    const float* wq1 = (const float*)d_in[7];
    const float* wk1 = (const float*)d_in[8];
    const float* wv1 = (const float*)d_in[9];
    const float* wo1 = (const float*)d_in[10];
    const float* g2  = (const float*)d_in[11];
    const float* b2  = (const float*)d_in[12];
    const float* wq2 = (const float*)d_in[13];
    const float* wk2 = (const float*)d_in[14];
    const float* wv2 = (const float*)d_in[15];
    const float* wo2 = (const float*)d_in[16];
    const float* g3  = (const float*)d_in[17];
    const float* b3  = (const float*)d_in[18];
    const float* wc1 = (const float*)d_in[19];
    const float* wc2 = (const float*)d_in[20];

    float* out0 = (float*)d_out;
    float* opq1 = out0 + 8 * FW;
    float* opq2 = opq1 + (size_t)NINST * QKSZ;

    float *nx, *q, *k, *v, *att, *z1, *z2, *nh, *n3, *tb, *rm, *rs;
    __nv_bfloat16 *qth, *qtl, *kth, *ktl, *vh, *vl;
    cudaGetSymbolAddress((void**)&nx,  g_nx);
    cudaGetSymbolAddress((void**)&q,   g_q);
    cudaGetSymbolAddress((void**)&k,   g_k);
    cudaGetSymbolAddress((void**)&v,   g_v);
    cudaGetSymbolAddress((void**)&att, g_att);
    cudaGetSymbolAddress((void**)&z1,  g_z1);
    cudaGetSymbolAddress((void**)&z2,  g_z2);
    cudaGetSymbolAddress((void**)&nh,  g_nh);
    cudaGetSymbolAddress((void**)&n3,  g_n3);
    cudaGetSymbolAddress((void**)&tb,  g_t);
    cudaGetSymbolAddress((void**)&rm,  g_rm);
    cudaGetSymbolAddress((void**)&rs,  g_rs);
    cudaGetSymbolAddress((void**)&qth, g_qth);
    cudaGetSymbolAddress((void**)&qtl, g_qtl);
    cudaGetSymbolAddress((void**)&kth, g_kth);
    cudaGetSymbolAddress((void**)&ktl, g_ktl);
    cudaGetSymbolAddress((void**)&vh,  g_vh);
    cudaGetSymbolAddress((void**)&vl,  g_vl);

    // ---- block 1: LN1 + self-attention on nx -----------------------------
    ln_kernel<<<dim3(4, 8), 128>>>(x, nullptr, nullptr, g1, b1, nx);
    conv1x3_multi<3><<<2048, 256>>>(nx, wq1, wk1, wv1, q, k, v, 8);
    split_trans_kernel<<<dim3(16, 4, NINST), dim3(32, 8)>>>(q, qth, qtl);
    split_trans_kernel<<<dim3(16, 4, NINST), dim3(32, 8)>>>(k, kth, ktl);
    split_v_kernel<<<4096, 256>>>(v, vh, vl);
    qk_mma_kernel<<<dim3(4, 4, NINST), 256>>>(qth, qtl, kth, ktl,
                                              prev_qk1, skip_qk, nullptr, opq1);
    rowstats_kernel<<<4096, 256>>>(opq1, rm, rs);
    av_mma_kernel<<<dim3(4, NINST), 256>>>(opq1, rm, rs, vh, vl, att);
    conv1x3_multi<1><<<2048, 256>>>(att, wo1, nullptr, nullptr, z1, nullptr, nullptr, 8);

    // ---- block 2: LN2 on [x, z1] + cross-attention vs skip ---------------
    ln_kernel<<<dim3(4, 16), 128>>>(x, z1, nullptr, g2, b2, nh);
    conv1x3_multi<1><<<2048, 256>>>(nh, wq2, nullptr, nullptr, q, nullptr, nullptr, 16);
    conv1x3_multi<2><<<2048, 256>>>(skip, wk2, wv2, nullptr, k, v, nullptr, 8);
    split_trans_kernel<<<dim3(16, 4, NINST), dim3(32, 8)>>>(q, qth, qtl);
    split_trans_kernel<<<dim3(16, 4, NINST), dim3(32, 8)>>>(k, kth, ktl);
    split_v_kernel<<<4096, 256>>>(v, vh, vl);
    qk_mma_kernel<<<dim3(4, 4, NINST), 256>>>(qth, qtl, kth, ktl,
                                              skip_qk, opq1, prev_qk2, opq2);
    rowstats_kernel<<<4096, 256>>>(opq2, rm, rs);
    av_mma_kernel<<<dim3(4, NINST), 256>>>(opq2, rm, rs, vh, vl, att);
    conv1x3_multi<1><<<2048, 256>>>(att, wo2, nullptr, nullptr, z2, nullptr, nullptr, 8);

    // ---- block 3: LN3 on [x, z1, z2] + conv MLP + residual ---------------
    ln_kernel<<<dim3(4, 24), 128>>>(x, z1, z2, g3, b3, n3);
    conv3x3_sq_kernel<<<2048, 256>>>(n3, wc1, tb);
    conv3x3_res_kernel<<<2048, 256>>>(tb, wc2, x, out0);
}

// round 13
// speedup vs baseline: 1.1903x; 1.0145x over previous
#include <cuda_runtime.h>
#include <cuda_bf16.h>
#include <math.h>
#include <stdint.h>

// ---------------------------------------------------------------------------
// FrameTransformerDecoder — qk & av via split-bf16 mma.sync; convs/LN fp32.
// R13: split_v fused into conv epilogue; q/k split_trans merged; launch order
// places qk_mma at profile slot 4.
// Shapes: B=1, C=8, OC=8, F=1024, W=512, H=8, d=128, EXP=4
// ---------------------------------------------------------------------------

#define F_DIM 1024
#define W_DIM 512
#define FW    (F_DIM * W_DIM)
#define NINST 64
#define QKSZ  (W_DIM * W_DIM)
#define LOG2E 1.4426950408889634f
#define QK_SCALE 0.0883883476483184f

// ------------------------- scratch (device globals) ------------------------
__device__ float g_nx [8  * FW];
__device__ float g_q  [8  * FW];
__device__ float g_k  [8  * FW];
__device__ float g_att[8  * FW];
__device__ float g_z1 [8  * FW];
__device__ float g_z2 [8  * FW];
__device__ float g_nh [16 * FW];
__device__ float g_n3 [24 * FW];
__device__ float g_t  [32 * FW];
__device__ float g_rm [NINST * W_DIM];
__device__ float g_rs [NINST * W_DIM];
// split-bf16 transposed q/k: [inst][w(512)][dd(128)]
__device__ __nv_bfloat16 g_qth[NINST * W_DIM * 128];
__device__ __nv_bfloat16 g_qtl[NINST * W_DIM * 128];
__device__ __nv_bfloat16 g_kth[NINST * W_DIM * 128];
__device__ __nv_bfloat16 g_ktl[NINST * W_DIM * 128];
// split-bf16 v in natural layout [inst*128+dd][w]
__device__ __nv_bfloat16 g_vh [8 * FW];
__device__ __nv_bfloat16 g_vl [8 * FW];

// ------------------------------ PTX helpers --------------------------------
__device__ __forceinline__ uint32_t smem_u32(const void* p) {
    uint32_t a;
    asm("{ .reg .u64 tmp; cvta.to.shared.u64 tmp, %1; cvt.u32.u64 %0, tmp; }"
        : "=r"(a) : "l"(p));
    return a;
}
__device__ __forceinline__ void ldsm4(uint32_t* r, uint32_t addr) {
    asm volatile("ldmatrix.sync.aligned.m8n8.x4.shared.b16 {%0,%1,%2,%3}, [%4];"
        : "=r"(r[0]), "=r"(r[1]), "=r"(r[2]), "=r"(r[3]) : "r"(addr));
}
__device__ __forceinline__ void mma16816(float* d, const uint32_t* a, const uint32_t* b) {
    asm volatile(
        "mma.sync.aligned.m16n8k16.row.col.f32.bf16.bf16.f32 "
        "{%0,%1,%2,%3}, {%4,%5,%6,%7}, {%8,%9}, {%0,%1,%2,%3};"
        : "+f"(d[0]), "+f"(d[1]), "+f"(d[2]), "+f"(d[3])
        : "r"(a[0]), "r"(a[1]), "r"(a[2]), "r"(a[3]), "r"(b[0]), "r"(b[1]));
}

// ------------------------------ LayerNorm ----------------------------------
__global__ __launch_bounds__(128)
void ln_kernel(const float* s0, const float* s1, const float* s2,
               const float* __restrict__ g, const float* __restrict__ b,
               float* __restrict__ out)
{
    int c = blockIdx.y;
    int w = blockIdx.x * 128 + threadIdx.x;
    const float* src = (c < 8) ? (s0 + c * FW)
                     : (c < 16) ? (s1 + (c - 8) * FW)
                                : (s2 + (c - 16) * FW);
    const float* p = src + w;
    float sum = 0.f, sq = 0.f;
    #pragma unroll 4
    for (int f = 0; f < F_DIM; f++) {
        float v = p[f * W_DIM];
        sum += v;
        sq = fmaf(v, v, sq);
    }
    float mu  = sum * (1.f / 1024.f);
    float var = sq * (1.f / 1024.f) - mu * mu;
    float inv = rsqrtf(var + 1e-8f);
    float* op = out + c * FW + w;
    const float* gp = g + c * F_DIM;
    const float* bp = b + c * F_DIM;
    #pragma unroll 4
    for (int f = 0; f < F_DIM; f++) {
        float v = p[f * W_DIM];
        op[f * W_DIM] = (v - mu) * inv * gp[f] + bp[f];
    }
}

// -------------------- 1x3 conv, NOUT projections ---------------------------
// If SPLIT_LAST, the last output is written only as bf16 hi/lo (vh/vl).
template<int NOUT, bool SPLIT_LAST>
__global__ __launch_bounds__(256)
void conv1x3_multi(const float* __restrict__ in,
                   const float* __restrict__ w0, const float* __restrict__ w1,
                   const float* __restrict__ w2,
                   float* __restrict__ o0, float* __restrict__ o1,
                   float* __restrict__ o2,
                   __nv_bfloat16* __restrict__ vh,
                   __nv_bfloat16* __restrict__ vl, int IC)
{
    __shared__ float ws[NOUT][8 * 16 * 3];
    int nw = 8 * IC * 3;
    for (int e = threadIdx.x; e < nw; e += 256) {
        ws[0][e] = w0[e];
        if (NOUT > 1) ws[1][e] = w1[e];
        if (NOUT > 2) ws[2][e] = w2[e];
    }
    __syncthreads();

    int p = blockIdx.x * 256 + threadIdx.x;
    int f = p >> 9, w = p & 511;
    float acc[NOUT][8];
    #pragma unroll
    for (int n = 0; n < NOUT; n++)
        #pragma unroll
        for (int o = 0; o < 8; o++) acc[n][o] = 0.f;

    for (int ic = 0; ic < IC; ic++) {
        const float* bp = in + (ic * F_DIM + f) * W_DIM + w;
        float m = bp[0];
        float l = (w > 0)   ? bp[-1] : 0.f;
        float r = (w < 511) ? bp[1]  : 0.f;
        #pragma unroll
        for (int n = 0; n < NOUT; n++) {
            #pragma unroll
            for (int o = 0; o < 8; o++) {
                const float* wp = ws[n] + (o * IC + ic) * 3;
                acc[n][o] = fmaf(l, wp[0], acc[n][o]);
                acc[n][o] = fmaf(m, wp[1], acc[n][o]);
                acc[n][o] = fmaf(r, wp[2], acc[n][o]);
            }
        }
    }
    float* outs[3] = {o0, o1, o2};
    #pragma unroll
    for (int n = 0; n < NOUT; n++) {
        if (SPLIT_LAST && n == NOUT - 1) {
            #pragma unroll
            for (int o = 0; o < 8; o++) {
                float val = acc[n][o];
                __nv_bfloat16 h = __float2bfloat16(val);
                __nv_bfloat16 lo = __float2bfloat16(val - __bfloat162float(h));
                size_t idx = (size_t)(o * F_DIM + f) * W_DIM + w;
                vh[idx] = h;
                vl[idx] = lo;
            }
        } else {
            #pragma unroll
            for (int o = 0; o < 8; o++)
                outs[n][(o * F_DIM + f) * W_DIM + w] = acc[n][o];
        }
    }
}

// ------------- transpose + split fp32 -> bf16 hi/lo, q AND k ---------------
// z < 64: q instance z; z >= 64: k instance z-64.
__global__ __launch_bounds__(256)
void split_qk_kernel(const float* __restrict__ qin, const float* __restrict__ kin,
                     __nv_bfloat16* __restrict__ qoh, __nv_bfloat16* __restrict__ qol,
                     __nv_bfloat16* __restrict__ koh, __nv_bfloat16* __restrict__ kol)
{
    __shared__ float tile[32][33];
    int z = blockIdx.z;
    int i = z & 63;
    bool isK = z >= 64;
    const float* in = isK ? kin : qin;
    __nv_bfloat16* oh = isK ? koh : qoh;
    __nv_bfloat16* ol = isK ? kol : qol;

    int w0 = blockIdx.x * 32, d0 = blockIdx.y * 32;
    int tx = threadIdx.x, ty = threadIdx.y;
    const float* ib = in + ((size_t)i * 128 + d0) * W_DIM + w0;
    #pragma unroll
    for (int j = ty; j < 32; j += 8)
        tile[j][tx] = ib[j * W_DIM + tx];
    __syncthreads();
    size_t ob = (size_t)i * (W_DIM * 128) + (size_t)w0 * 128 + d0;
    #pragma unroll
    for (int j = ty; j < 32; j += 8) {
        float x = tile[tx][j];
        __nv_bfloat16 h = __float2bfloat16(x);
        float hf = __bfloat162float(h);
        __nv_bfloat16 l = __float2bfloat16(x - hf);
        oh[ob + (size_t)j * 128 + tx] = h;
        ol[ob + (size_t)j * 128 + tx] = l;
    }
}

// ------------------------- QK GEMM via mma.sync ----------------------------
// out[i,q,k] = SCALE * sum_d Q[q,d]*K[k,d] + b0 + b1 (+ b2)
// CTA 128q x 128k, 8 warps (2m x 4n), warp 64x32, K staged in 32-d chunks.
__global__ __launch_bounds__(256)
void qk_mma_kernel(const __nv_bfloat16* __restrict__ qh, const __nv_bfloat16* __restrict__ ql,
                   const __nv_bfloat16* __restrict__ kh, const __nv_bfloat16* __restrict__ kl,
                   const float* __restrict__ b0, const float* __restrict__ b1,
                   const float* __restrict__ b2, float* __restrict__ out)
{
    __shared__ __align__(16) __nv_bfloat16 sQh[128][40];
    __shared__ __align__(16) __nv_bfloat16 sQl[128][40];
    __shared__ __align__(16) __nv_bfloat16 sKh[128][40];
    __shared__ __align__(16) __nv_bfloat16 sKl[128][40];

    int i = blockIdx.z, k0 = blockIdx.x << 7, q0 = blockIdx.y << 7;
    int t = threadIdx.x, wid = t >> 5, lane = t & 31;
    int wm = (wid >> 2) * 64, wn = (wid & 3) * 32;

    const __nv_bfloat16* qhg = qh + ((size_t)i * W_DIM + q0) * 128;
    const __nv_bfloat16* qlg = ql + ((size_t)i * W_DIM + q0) * 128;
    const __nv_bfloat16* khg = kh + ((size_t)i * W_DIM + k0) * 128;
    const __nv_bfloat16* klg = kl + ((size_t)i * W_DIM + k0) * 128;

    float acc[4][4][4];
    #pragma unroll
    for (int m = 0; m < 4; m++)
        #pragma unroll
        for (int n = 0; n < 4; n++)
            #pragma unroll
            for (int r = 0; r < 4; r++) acc[m][n][r] = 0.f;

    for (int d0 = 0; d0 < 128; d0 += 32) {
        {
            int row = t & 127;
            const uint4* g0; const uint4* g1; uint4* s0; uint4* s1;
            if (t < 128) {
                g0 = (const uint4*)(qhg + (size_t)row * 128 + d0);
                g1 = (const uint4*)(qlg + (size_t)row * 128 + d0);
                s0 = (uint4*)&sQh[row][0];
                s1 = (uint4*)&sQl[row][0];
            } else {
                g0 = (const uint4*)(khg + (size_t)row * 128 + d0);
                g1 = (const uint4*)(klg + (size_t)row * 128 + d0);
                s0 = (uint4*)&sKh[row][0];
                s1 = (uint4*)&sKl[row][0];
            }
            #pragma unroll
            for (int c2 = 0; c2 < 4; c2++) { s0[c2] = g0[c2]; s1[c2] = g1[c2]; }
        }
        __syncthreads();
        #pragma unroll
        for (int kk = 0; kk < 32; kk += 16) {
            int arow = lane & 15;
            int ac = kk + (lane >> 4) * 8;
            uint32_t bh[8], bl[8];
            ldsm4(bh,     smem_u32(&sKh[wn + arow][ac]));
            ldsm4(bh + 4, smem_u32(&sKh[wn + 16 + arow][ac]));
            ldsm4(bl,     smem_u32(&sKl[wn + arow][ac]));
            ldsm4(bl + 4, smem_u32(&sKl[wn + 16 + arow][ac]));
            #pragma unroll
            for (int m = 0; m < 4; m++) {
                uint32_t ah[4], al[4];
                ldsm4(ah, smem_u32(&sQh[wm + m * 16 + arow][ac]));
                ldsm4(al, smem_u32(&sQl[wm + m * 16 + arow][ac]));
                #pragma unroll
                for (int n = 0; n < 4; n++) {
                    int bi = (n >> 1) * 4 + (n & 1);
                    uint32_t fh[2] = {bh[bi], bh[bi + 2]};
                    uint32_t fl[2] = {bl[bi], bl[bi + 2]};
                    mma16816(acc[m][n], ah, fh);
                    mma16816(acc[m][n], ah, fl);
                    mma16816(acc[m][n], al, fh);
                }
            }
        }
        __syncthreads();
    }

    int g = lane >> 2, c = lane & 3;
    #pragma unroll
    for (int m = 0; m < 4; m++) {
        #pragma unroll
        for (int n = 0; n < 4; n++) {
            int col = k0 + wn + n * 8 + c * 2;
            #pragma unroll
            for (int h2 = 0; h2 < 2; h2++) {
                int row = q0 + wm + m * 16 + g + h2 * 8;
                size_t idx = (size_t)i * QKSZ + (size_t)row * W_DIM + col;
                float vx = acc[m][n][h2 * 2 + 0] * QK_SCALE + b0[idx] + b1[idx];
                float vy = acc[m][n][h2 * 2 + 1] * QK_SCALE + b0[idx + 1] + b1[idx + 1];
                if (b2) { vx += b2[idx]; vy += b2[idx + 1]; }
                *(float2*)(out + idx) = make_float2(vx, vy);
            }
        }
    }
}

// ---------------------------- softmax rowstats -----------------------------
__global__ __launch_bounds__(256)
void rowstats_kernel(const float* __restrict__ qk, float* __restrict__ rm,
                     float* __restrict__ rs)
{
    int row  = blockIdx.x * 8 + (threadIdx.x >> 5);
    int lane = threadIdx.x & 31;
    const float4* p = (const float4*)(qk + (size_t)row * W_DIM);
    float4 vals[4];
    float mx = -1e30f;
    #pragma unroll
    for (int j = 0; j < 4; j++) {
        float4 v = p[lane + j * 32];
        vals[j] = v;
        mx = fmaxf(mx, fmaxf(fmaxf(v.x, v.y), fmaxf(v.z, v.w)));
    }
    #pragma unroll
    for (int o = 16; o > 0; o >>= 1)
        mx = fmaxf(mx, __shfl_xor_sync(0xffffffffu, mx, o));
    float s = 0.f;
    #pragma unroll
    for (int j = 0; j < 4; j++) {
        float4 v = vals[j];
        s += exp2f((v.x - mx) * LOG2E) + exp2f((v.y - mx) * LOG2E)
           + exp2f((v.z - mx) * LOG2E) + exp2f((v.w - mx) * LOG2E);
    }
    #pragma unroll
    for (int o = 16; o > 0; o >>= 1)
        s += __shfl_xor_sync(0xffffffffu, s, o);
    if (lane == 0) { rm[row] = mx; rs[row] = 1.f / s; }
}

// ------------------------- AV GEMM via mma.sync ----------------------------
// att[i*128+dd][q] = sum_k softmax(qk)[q,k] * V[dd,k]
__global__ __launch_bounds__(256)
void av_mma_kernel(const float* __restrict__ qk, const float* __restrict__ rm,
                   const float* __restrict__ rs,
                   const __nv_bfloat16* __restrict__ vh,
                   const __nv_bfloat16* __restrict__ vl,
                   float* __restrict__ att)
{
    __shared__ __align__(16) __nv_bfloat16 sPh[128][40];
    __shared__ __align__(16) __nv_bfloat16 sPl[128][40];
    __shared__ __align__(16) __nv_bfloat16 sVh[128][40];
    __shared__ __align__(16) __nv_bfloat16 sVl[128][40];

    int i = blockIdx.y, q0 = blockIdx.x << 7;
    int t = threadIdx.x, wid = t >> 5, lane = t & 31;
    int wm = (wid >> 2) * 64, wn = (wid & 3) * 32;

    const float* qkb = qk + (size_t)i * QKSZ;
    const __nv_bfloat16* vhb = vh + (size_t)i * 128 * W_DIM;
    const __nv_bfloat16* vlb = vl + (size_t)i * 128 * W_DIM;
    float* attb = att + (size_t)i * 128 * W_DIM;

    int prow = t >> 1, pch = (t & 1) * 16;
    float mrow = rm[i * W_DIM + q0 + prow];
    float srow = rs[i * W_DIM + q0 + prow];
    const float4* prows = (const float4*)(qkb + (size_t)(q0 + prow) * W_DIM + pch);

    float acc[4][4][4];
    #pragma unroll
    for (int m = 0; m < 4; m++)
        #pragma unroll
        for (int n = 0; n < 4; n++)
            #pragma unroll
            for (int r = 0; r < 4; r++) acc[m][n][r] = 0.f;

    for (int k0c = 0; k0c < 512; k0c += 32) {
        {
            union { uint4 u[2]; __nv_bfloat16 h[16]; } H, L;
            #pragma unroll
            for (int j = 0; j < 4; j++) {
                float4 p4 = prows[(k0c >> 2) + j];
                float e[4];
                e[0] = exp2f((p4.x - mrow) * LOG2E) * srow;
                e[1] = exp2f((p4.y - mrow) * LOG2E) * srow;
                e[2] = exp2f((p4.z - mrow) * LOG2E) * srow;
                e[3] = exp2f((p4.w - mrow) * LOG2E) * srow;
                #pragma unroll
                for (int x2 = 0; x2 < 4; x2++) {
                    __nv_bfloat16 hh = __float2bfloat16(e[x2]);
                    H.h[j * 4 + x2] = hh;
                    L.h[j * 4 + x2] = __float2bfloat16(e[x2] - __bfloat162float(hh));
                }
            }
            *(uint4*)&sPh[prow][pch]     = H.u[0];
            *(uint4*)&sPh[prow][pch + 8] = H.u[1];
            *(uint4*)&sPl[prow][pch]     = L.u[0];
            *(uint4*)&sPl[prow][pch + 8] = L.u[1];
            if (t < 128) {
                const uint4* gv0 = (const uint4*)(vhb + (size_t)t * W_DIM + k0c);
                const uint4* gv1 = (const uint4*)(vlb + (size_t)t * W_DIM + k0c);
                uint4* s0 = (uint4*)&sVh[t][0];
                uint4* s1 = (uint4*)&sVl[t][0];
                #pragma unroll
                for (int c2 = 0; c2 < 4; c2++) { s0[c2] = gv0[c2]; s1[c2] = gv1[c2]; }
            }
        }
        __syncthreads();
        #pragma unroll
        for (int kk = 0; kk < 32; kk += 16) {
            int arow = lane & 15;
            int ac = kk + (lane >> 4) * 8;
            uint32_t bh[8], bl[8];
            ldsm4(bh,     smem_u32(&sVh[wn + arow][ac]));
            ldsm4(bh + 4, smem_u32(&sVh[wn + 16 + arow][ac]));
            ldsm4(bl,     smem_u32(&sVl[wn + arow][ac]));
            ldsm4(bl + 4, smem_u32(&sVl[wn + 16 + arow][ac]));
            #pragma unroll
            for (int m = 0; m < 4; m++) {
                uint32_t ah[4], al[4];
                ldsm4(ah, smem_u32(&sPh[wm + m * 16 + arow][ac]));
                ldsm4(al, smem_u32(&sPl[wm + m * 16 + arow][ac]));
                #pragma unroll
                for (int n = 0; n < 4; n++) {
                    int bi = (n >> 1) * 4 + (n & 1);
                    uint32_t fh[2] = {bh[bi], bh[bi + 2]};
                    uint32_t fl[2] = {bl[bi], bl[bi + 2]};
                    mma16816(acc[m][n], ah, fh);
                    mma16816(acc[m][n], ah, fl);
                    mma16816(acc[m][n], al, fh);
                }
            }
        }
        __syncthreads();
    }

    int g = lane >> 2, c = lane & 3;
    #pragma unroll
    for (int m = 0; m < 4; m++) {
        #pragma unroll
        for (int n = 0; n < 4; n++) {
            int dd = wn + n * 8 + c * 2;
            #pragma unroll
            for (int h2 = 0; h2 < 2; h2++) {
                int row = q0 + wm + m * 16 + g + h2 * 8;
                attb[(size_t)dd * W_DIM + row]       = acc[m][n][h2 * 2 + 0];
                attb[(size_t)(dd + 1) * W_DIM + row] = acc[m][n][h2 * 2 + 1];
            }
        }
    }
}

// --------------------- 3x3 conv 24->32 + SquaredReLU -----------------------
__global__ __launch_bounds__(256)
void conv3x3_sq_kernel(const float* __restrict__ in, const float* __restrict__ wgt,
                       float* __restrict__ out)
{
    __shared__ __align__(16) float ws[216 * 32];
    for (int e = threadIdx.x; e < 216 * 32; e += 256) {
        int o = e & 31, idx = e >> 5;
        ws[e] = wgt[o * 216 + idx];
    }
    __syncthreads();

    int p = blockIdx.x * 256 + threadIdx.x;
    int f = p >> 9, w = p & 511;
    float acc[32];
    #pragma unroll
    for (int o = 0; o < 32; o++) acc[o] = 0.f;

    for (int ic = 0; ic < 24; ic++) {
        #pragma unroll
        for (int ky = 0; ky < 3; ky++) {
            int ff = f + ky - 1;
            if ((unsigned)ff >= (unsigned)F_DIM) continue;
            const float* rp = in + (ic * F_DIM + ff) * W_DIM;
            #pragma unroll
            for (int kx = 0; kx < 3; kx++) {
                int ww = w + kx - 1;
                if ((unsigned)ww >= (unsigned)W_DIM) continue;
                float v = rp[ww];
                const float4* wp = (const float4*)&ws[(ic * 9 + ky * 3 + kx) * 32];
                #pragma unroll
                for (int o4 = 0; o4 < 8; o4++) {
                    float4 wv = wp[o4];
                    acc[o4 * 4 + 0] = fmaf(v, wv.x, acc[o4 * 4 + 0]);
                    acc[o4 * 4 + 1] = fmaf(v, wv.y, acc[o4 * 4 + 1]);
                    acc[o4 * 4 + 2] = fmaf(v, wv.z, acc[o4 * 4 + 2]);
                    acc[o4 * 4 + 3] = fmaf(v, wv.w, acc[o4 * 4 + 3]);
                }
            }
        }
    }
    #pragma unroll
    for (int o = 0; o < 32; o++) {
        float r = fmaxf(acc[o], 0.f);
        out[(o * F_DIM + f) * W_DIM + w] = r * r;
    }
}

// --------------------- 3x3 conv 32->8 + residual ---------------------------
__global__ __launch_bounds__(256)
void conv3x3_res_kernel(const float* __restrict__ in, const float* __restrict__ wgt,
                        const float* __restrict__ xin, float* __restrict__ out)
{
    __shared__ __align__(16) float ws[288 * 8];
    for (int e = threadIdx.x; e < 288 * 8; e += 256) {
        int o = e & 7, idx = e >> 3;
        ws[e] = wgt[o * 288 + idx];
    }
    __syncthreads();

    int p = blockIdx.x * 256 + threadIdx.x;
    int f = p >> 9, w = p & 511;
    float acc[8] = {0.f, 0.f, 0.f, 0.f, 0.f, 0.f, 0.f, 0.f};

    for (int ic = 0; ic < 32; ic++) {
        #pragma unroll
        for (int ky = 0; ky < 3; ky++) {
            int ff = f + ky - 1;
            if ((unsigned)ff >= (unsigned)F_DIM) continue;
            const float* rp = in + (ic * F_DIM + ff) * W_DIM;
            #pragma unroll
            for (int kx = 0; kx < 3; kx++) {
                int ww = w + kx - 1;
                if ((unsigned)ww >= (unsigned)W_DIM) continue;
                float v = rp[ww];
                const float4* wp = (const float4*)&ws[(ic * 9 + ky * 3 + kx) * 8];
                float4 w0 = wp[0], w1 = wp[1];
                acc[0] = fmaf(v, w0.x, acc[0]);
                acc[1] = fmaf(v, w0.y, acc[1]);
                acc[2] = fmaf(v, w0.z, acc[2]);
                acc[3] = fmaf(v, w0.w, acc[3]);
                acc[4] = fmaf(v, w1.x, acc[4]);
                acc[5] = fmaf(v, w1.y, acc[5]);
                acc[6] = fmaf(v, w1.z, acc[6]);
                acc[7] = fmaf(v, w1.w, acc[7]);
            }
        }
    }
    #pragma unroll
    for (int o = 0; o < 8; o++) {
        int idx = (o * F_DIM + f) * W_DIM + w;
        out[idx] = xin[idx] + acc[o];
    }
}

// ------------------------------- launcher ----------------------------------
extern "C" void kernel_launch(void* const* d_in, const int* in_sizes, int n_in,
                              void* d_out, int out_size)
{
    (void)in_sizes; (void)n_in; (void)out_size;

    const float* x        = (const float*)d_in[0];
    const float* skip     = (const float*)d_in[1];
    const float* prev_qk1 = (const float*)d_in[2];
    const float* prev_qk2 = (const float*)d_in[3];
    const float* skip_qk  = (const float*)d_in[4];
    const float* g1  = (const float*)d_in[5];
    const float* b1  = (const float*)d_in[6];
    const float* wq1 = (const float*)d_in[7];
    const float* wk1 = (const float*)d_in[8];
    const float* wv1 = (const float*)d_in[9];
    const float* wo1 = (const float*)d_in[10];
    const float* g2  = (const float*)d_in[11];
    const float* b2  = (const float*)d_in[12];
    const float* wq2 = (const float*)d_in[13];
    const float* wk2 = (const float*)d_in[14];
    const float* wv2 = (const float*)d_in[15];
    const float* wo2 = (const float*)d_in[16];
    const float* g3  = (const float*)d_in[17];
    const float* b3  = (const float*)d_in[18];
    const float* wc1 = (const float*)d_in[19];
    const float* wc2 = (const float*)d_in[20];

    float* out0 = (float*)d_out;
    float* opq1 = out0 + 8 * FW;
    float* opq2 = opq1 + (size_t)NINST * QKSZ;

    float *nx, *q, *k, *att, *z1, *z2, *nh, *n3, *tb, *rm, *rs;
    __nv_bfloat16 *qth, *qtl, *kth, *ktl, *vh, *vl;
    cudaGetSymbolAddress((void**)&nx,  g_nx);
    cudaGetSymbolAddress((void**)&q,   g_q);
    cudaGetSymbolAddress((void**)&k,   g_k);
    cudaGetSymbolAddress((void**)&att, g_att);
    cudaGetSymbolAddress((void**)&z1,  g_z1);
    cudaGetSymbolAddress((void**)&z2,  g_z2);
    cudaGetSymbolAddress((void**)&nh,  g_nh);
    cudaGetSymbolAddress((void**)&n3,  g_n3);
    cudaGetSymbolAddress((void**)&tb,  g_t);
    cudaGetSymbolAddress((void**)&rm,  g_rm);
    cudaGetSymbolAddress((void**)&rs,  g_rs);
    cudaGetSymbolAddress((void**)&qth, g_qth);
    cudaGetSymbolAddress((void**)&qtl, g_qtl);
    cudaGetSymbolAddress((void**)&kth, g_kth);
    cudaGetSymbolAddress((void**)&ktl, g_ktl);
    cudaGetSymbolAddress((void**)&vh,  g_vh);
    cudaGetSymbolAddress((void**)&vl,  g_vl);

    // ---- block 1: LN1 + self-attention on nx -----------------------------
    ln_kernel<<<dim3(4, 8), 128>>>(x, nullptr, nullptr, g1, b1, nx);           // 1
    conv1x3_multi<3, true><<<2048, 256>>>(nx, wq1, wk1, wv1,
                                          q, k, nullptr, vh, vl, 8);           // 2
    split_qk_kernel<<<dim3(16, 4, 128), dim3(32, 8)>>>(q, k,
                                          qth, qtl, kth, ktl);                 // 3
    qk_mma_kernel<<<dim3(4, 4, NINST), 256>>>(qth, qtl, kth, ktl,
                                          prev_qk1, skip_qk, nullptr, opq1);   // 4 (profiled)
    rowstats_kernel<<<4096, 256>>>(opq1, rm, rs);                              // 5
    av_mma_kernel<<<dim3(4, NINST), 256>>>(opq1, rm, rs, vh, vl, att);         // 6
    conv1x3_multi<1, false><<<2048, 256>>>(att, wo1, nullptr, nullptr,
                                          z1, nullptr, nullptr,
                                          nullptr, nullptr, 8);                // 7

    // ---- block 2: LN2 on [x, z1] + cross-attention vs skip ---------------
    ln_kernel<<<dim3(4, 16), 128>>>(x, z1, nullptr, g2, b2, nh);               // 8
    conv1x3_multi<1, false><<<2048, 256>>>(nh, wq2, nullptr, nullptr,
                                          q, nullptr, nullptr,
                                          nullptr, nullptr, 16);               // 9
    conv1x3_multi<2, true><<<2048, 256>>>(skip, wk2, wv2, nullptr,
                                          k, nullptr, nullptr, vh, vl, 8);     // 10
    split_qk_kernel<<<dim3(16, 4, 128), dim3(32, 8)>>>(q, k,
                                          qth, qtl, kth, ktl);                 // 11
    qk_mma_kernel<<<dim3(4, 4, NINST), 256>>>(qth, qtl, kth, ktl,
                                          skip_qk, opq1, prev_qk2, opq2);      // 12
    rowstats_kernel<<<4096, 256>>>(opq2, rm, rs);                              // 13
    av_mma_kernel<<<dim3(4, NINST), 256>>>(opq2, rm, rs, vh, vl, att);         // 14
    conv1x3_multi<1, false><<<2048, 256>>>(att, wo2, nullptr, nullptr,
                                          z2, nullptr, nullptr,
                                          nullptr, nullptr, 8);                // 15

    // ---- block 3: LN3 on [x, z1, z2] + conv MLP + residual ---------------
    ln_kernel<<<dim3(4, 24), 128>>>(x, z1, z2, g3, b3, n3);                    // 16
    conv3x3_sq_kernel<<<2048, 256>>>(n3, wc1, tb);                             // 17
    conv3x3_res_kernel<<<2048, 256>>>(tb, wc2, x, out0);                       // 18
}

// round 15
// speedup vs baseline: 1.1967x; 1.0054x over previous
#include <cuda_runtime.h>
#include <cuda_bf16.h>
#include <math.h>
#include <stdint.h>

// ---------------------------------------------------------------------------
// FrameTransformerDecoder — qk & av via split-bf16 mma.sync with cp.async
// double-buffered pipelines; convs/LN fp32 SIMT.
// R15: fixes R14's av chunk-count bug (16 chunks over K=512, not 4).
// Shapes: B=1, C=8, OC=8, F=1024, W=512, H=8, d=128, EXP=4
// ---------------------------------------------------------------------------

#define F_DIM 1024
#define W_DIM 512
#define FW    (F_DIM * W_DIM)
#define NINST 64
#define QKSZ  (W_DIM * W_DIM)
#define LOG2E 1.4426950408889634f
#define QK_SCALE 0.0883883476483184f

#define MMA_ASZ   (128 * 40)             // elements per smem array (row stride 40)
#define MMA_SMEM  (2 * 4 * MMA_ASZ * 2)  // 2 bufs x 4 arrays x bytes = 81920

// ------------------------- scratch (device globals) ------------------------
__device__ float g_nx [8  * FW];
__device__ float g_q  [8  * FW];
__device__ float g_k  [8  * FW];
__device__ float g_att[8  * FW];
__device__ float g_z1 [8  * FW];
__device__ float g_z2 [8  * FW];
__device__ float g_nh [16 * FW];
__device__ float g_n3 [24 * FW];
__device__ float g_t  [32 * FW];
__device__ float g_rm [NINST * W_DIM];
__device__ float g_rs [NINST * W_DIM];
// split-bf16 transposed q/k: [inst][w(512)][dd(128)]
__device__ __nv_bfloat16 g_qth[NINST * W_DIM * 128];
__device__ __nv_bfloat16 g_qtl[NINST * W_DIM * 128];
__device__ __nv_bfloat16 g_kth[NINST * W_DIM * 128];
__device__ __nv_bfloat16 g_ktl[NINST * W_DIM * 128];
// split-bf16 v in natural layout [inst*128+dd][w]
__device__ __nv_bfloat16 g_vh [8 * FW];
__device__ __nv_bfloat16 g_vl [8 * FW];

// ------------------------------ PTX helpers --------------------------------
__device__ __forceinline__ uint32_t smem_u32(const void* p) {
    uint32_t a;
    asm("{ .reg .u64 tmp; cvta.to.shared.u64 tmp, %1; cvt.u32.u64 %0, tmp; }"
        : "=r"(a) : "l"(p));
    return a;
}
__device__ __forceinline__ void ldsm4(uint32_t* r, uint32_t addr) {
    asm volatile("ldmatrix.sync.aligned.m8n8.x4.shared.b16 {%0,%1,%2,%3}, [%4];"
        : "=r"(r[0]), "=r"(r[1]), "=r"(r[2]), "=r"(r[3]) : "r"(addr));
}
__device__ __forceinline__ void mma16816(float* d, const uint32_t* a, const uint32_t* b) {
    asm volatile(
        "mma.sync.aligned.m16n8k16.row.col.f32.bf16.bf16.f32 "
        "{%0,%1,%2,%3}, {%4,%5,%6,%7}, {%8,%9}, {%0,%1,%2,%3};"
        : "+f"(d[0]), "+f"(d[1]), "+f"(d[2]), "+f"(d[3])
        : "r"(a[0]), "r"(a[1]), "r"(a[2]), "r"(a[3]), "r"(b[0]), "r"(b[1]));
}
__device__ __forceinline__ void cp16(uint32_t s, const void* g) {
    asm volatile("cp.async.cg.shared.global [%0], [%1], 16;" :: "r"(s), "l"(g));
}
#define CP_COMMIT() asm volatile("cp.async.commit_group;" ::: "memory")
#define CP_WAIT1()  asm volatile("cp.async.wait_group 1;" ::: "memory")
#define CP_WAIT0()  asm volatile("cp.async.wait_group 0;" ::: "memory")

// ------------------------------ LayerNorm ----------------------------------
__global__ __launch_bounds__(128)
void ln_kernel(const float* s0, const float* s1, const float* s2,
               const float* __restrict__ g, const float* __restrict__ b,
               float* __restrict__ out)
{
    int c = blockIdx.y;
    int w = blockIdx.x * 128 + threadIdx.x;
    const float* src = (c < 8) ? (s0 + c * FW)
                     : (c < 16) ? (s1 + (c - 8) * FW)
                                : (s2 + (c - 16) * FW);
    const float* p = src + w;
    float sum = 0.f, sq = 0.f;
    #pragma unroll 4
    for (int f = 0; f < F_DIM; f++) {
        float v = p[f * W_DIM];
        sum += v;
        sq = fmaf(v, v, sq);
    }
    float mu  = sum * (1.f / 1024.f);
    float var = sq * (1.f / 1024.f) - mu * mu;
    float inv = rsqrtf(var + 1e-8f);
    float* op = out + c * FW + w;
    const float* gp = g + c * F_DIM;
    const float* bp = b + c * F_DIM;
    #pragma unroll 4
    for (int f = 0; f < F_DIM; f++) {
        float v = p[f * W_DIM];
        op[f * W_DIM] = (v - mu) * inv * gp[f] + bp[f];
    }
}

// -------------------- 1x3 conv, NOUT projections ---------------------------
template<int NOUT, bool SPLIT_LAST>
__global__ __launch_bounds__(256)
void conv1x3_multi(const float* __restrict__ in,
                   const float* __restrict__ w0, const float* __restrict__ w1,
                   const float* __restrict__ w2,
                   float* __restrict__ o0, float* __restrict__ o1,
                   float* __restrict__ o2,
                   __nv_bfloat16* __restrict__ vh,
                   __nv_bfloat16* __restrict__ vl, int IC)
{
    __shared__ float ws[NOUT][8 * 16 * 3];
    int nw = 8 * IC * 3;
    for (int e = threadIdx.x; e < nw; e += 256) {
        ws[0][e] = w0[e];
        if (NOUT > 1) ws[1][e] = w1[e];
        if (NOUT > 2) ws[2][e] = w2[e];
    }
    __syncthreads();

    int p = blockIdx.x * 256 + threadIdx.x;
    int f = p >> 9, w = p & 511;
    float acc[NOUT][8];
    #pragma unroll
    for (int n = 0; n < NOUT; n++)
        #pragma unroll
        for (int o = 0; o < 8; o++) acc[n][o] = 0.f;

    for (int ic = 0; ic < IC; ic++) {
        const float* bp = in + (ic * F_DIM + f) * W_DIM + w;
        float m = bp[0];
        float l = (w > 0)   ? bp[-1] : 0.f;
        float r = (w < 511) ? bp[1]  : 0.f;
        #pragma unroll
        for (int n = 0; n < NOUT; n++) {
            #pragma unroll
            for (int o = 0; o < 8; o++) {
                const float* wp = ws[n] + (o * IC + ic) * 3;
                acc[n][o] = fmaf(l, wp[0], acc[n][o]);
                acc[n][o] = fmaf(m, wp[1], acc[n][o]);
                acc[n][o] = fmaf(r, wp[2], acc[n][o]);
            }
        }
    }
    float* outs[3] = {o0, o1, o2};
    #pragma unroll
    for (int n = 0; n < NOUT; n++) {
        if (SPLIT_LAST && n == NOUT - 1) {
            #pragma unroll
            for (int o = 0; o < 8; o++) {
                float val = acc[n][o];
                __nv_bfloat16 h = __float2bfloat16(val);
                __nv_bfloat16 lo = __float2bfloat16(val - __bfloat162float(h));
                size_t idx = (size_t)(o * F_DIM + f) * W_DIM + w;
                vh[idx] = h;
                vl[idx] = lo;
            }
        } else {
            #pragma unroll
            for (int o = 0; o < 8; o++)
                outs[n][(o * F_DIM + f) * W_DIM + w] = acc[n][o];
        }
    }
}

// ------------- transpose + split fp32 -> bf16 hi/lo, q AND k ---------------
__global__ __launch_bounds__(256)
void split_qk_kernel(const float* __restrict__ qin, const float* __restrict__ kin,
                     __nv_bfloat16* __restrict__ qoh, __nv_bfloat16* __restrict__ qol,
                     __nv_bfloat16* __restrict__ koh, __nv_bfloat16* __restrict__ kol)
{
    __shared__ float tile[32][33];
    int z = blockIdx.z;
    int i = z & 63;
    bool isK = z >= 64;
    const float* in = isK ? kin : qin;
    __nv_bfloat16* oh = isK ? koh : qoh;
    __nv_bfloat16* ol = isK ? kol : qol;

    int w0 = blockIdx.x * 32, d0 = blockIdx.y * 32;
    int tx = threadIdx.x, ty = threadIdx.y;
    const float* ib = in + ((size_t)i * 128 + d0) * W_DIM + w0;
    #pragma unroll
    for (int j = ty; j < 32; j += 8)
        tile[j][tx] = ib[j * W_DIM + tx];
    __syncthreads();
    size_t ob = (size_t)i * (W_DIM * 128) + (size_t)w0 * 128 + d0;
    #pragma unroll
    for (int j = ty; j < 32; j += 8) {
        float x = tile[tx][j];
        __nv_bfloat16 h = __float2bfloat16(x);
        float hf = __bfloat162float(h);
        __nv_bfloat16 l = __float2bfloat16(x - hf);
        oh[ob + (size_t)j * 128 + tx] = h;
        ol[ob + (size_t)j * 128 + tx] = l;
    }
}

// ------------------------- QK GEMM via mma.sync ----------------------------
// out[i,q,k] = SCALE * sum_d Q[q,d]*K[k,d] + b0 + b1 (+ b2)
// CTA 128q x 128k, 8 warps (2m x 4n), warp 64x32; cp.async 2-deep pipeline
// over four 32-d chunks. Dynamic smem: 2 bufs x {Qh,Ql,Kh,Kl} x 128x40 bf16.
__global__ __launch_bounds__(256)
void qk_mma_kernel(const __nv_bfloat16* __restrict__ qh, const __nv_bfloat16* __restrict__ ql,
                   const __nv_bfloat16* __restrict__ kh, const __nv_bfloat16* __restrict__ kl,
                   const float* __restrict__ b0, const float* __restrict__ b1,
                   const float* __restrict__ b2, float* __restrict__ out)
{
    extern __shared__ __nv_bfloat16 dsm[];
    int i = blockIdx.z, k0 = blockIdx.x << 7, q0 = blockIdx.y << 7;
    int t = threadIdx.x, wid = t >> 5, lane = t & 31;
    int wm = (wid >> 2) * 64, wn = (wid & 3) * 32;

    const __nv_bfloat16* qhg = qh + ((size_t)i * W_DIM + q0) * 128;
    const __nv_bfloat16* qlg = ql + ((size_t)i * W_DIM + q0) * 128;
    const __nv_bfloat16* khg = kh + ((size_t)i * W_DIM + k0) * 128;
    const __nv_bfloat16* klg = kl + ((size_t)i * W_DIM + k0) * 128;

    // staging role: t<128 -> Q row t; t>=128 -> K row t-128
    int row = t & 127;
    const __nv_bfloat16* gH = ((t < 128) ? qhg : khg) + (size_t)row * 128;
    const __nv_bfloat16* gL = ((t < 128) ? qlg : klg) + (size_t)row * 128;
    int whichH = (t < 128) ? 0 : 2;

    auto issue = [&](int c, int buf) {
        uint32_t sh = smem_u32(dsm + (size_t)(buf * 4 + whichH) * MMA_ASZ + row * 40);
        uint32_t sl = smem_u32(dsm + (size_t)(buf * 4 + whichH + 1) * MMA_ASZ + row * 40);
        const __nv_bfloat16* ghc = gH + c * 32;
        const __nv_bfloat16* glc = gL + c * 32;
        #pragma unroll
        for (int j = 0; j < 4; j++) {
            cp16(sh + j * 16, ghc + j * 8);
            cp16(sl + j * 16, glc + j * 8);
        }
        CP_COMMIT();
    };

    float acc[4][4][4];
    #pragma unroll
    for (int m = 0; m < 4; m++)
        #pragma unroll
        for (int n = 0; n < 4; n++)
            #pragma unroll
            for (int r = 0; r < 4; r++) acc[m][n][r] = 0.f;

    issue(0, 0);
    for (int c = 0; c < 4; c++) {      // d = 128 -> 4 chunks of 32
        if (c < 3) { issue(c + 1, (c + 1) & 1); CP_WAIT1(); }
        else       { CP_WAIT0(); }
        __syncthreads();
        __nv_bfloat16 (*sQh)[40] = (__nv_bfloat16(*)[40])(dsm + (size_t)((c & 1) * 4 + 0) * MMA_ASZ);
        __nv_bfloat16 (*sQl)[40] = (__nv_bfloat16(*)[40])(dsm + (size_t)((c & 1) * 4 + 1) * MMA_ASZ);
        __nv_bfloat16 (*sKh)[40] = (__nv_bfloat16(*)[40])(dsm + (size_t)((c & 1) * 4 + 2) * MMA_ASZ);
        __nv_bfloat16 (*sKl)[40] = (__nv_bfloat16(*)[40])(dsm + (size_t)((c & 1) * 4 + 3) * MMA_ASZ);
        #pragma unroll
        for (int kk = 0; kk < 32; kk += 16) {
            int arow = lane & 15;
            int ac = kk + (lane >> 4) * 8;
            uint32_t bh[8], bl[8];
            ldsm4(bh,     smem_u32(&sKh[wn + arow][ac]));
            ldsm4(bh + 4, smem_u32(&sKh[wn + 16 + arow][ac]));
            ldsm4(bl,     smem_u32(&sKl[wn + arow][ac]));
            ldsm4(bl + 4, smem_u32(&sKl[wn + 16 + arow][ac]));
            #pragma unroll
            for (int m = 0; m < 4; m++) {
                uint32_t ah[4], al[4];
                ldsm4(ah, smem_u32(&sQh[wm + m * 16 + arow][ac]));
                ldsm4(al, smem_u32(&sQl[wm + m * 16 + arow][ac]));
                #pragma unroll
                for (int n = 0; n < 4; n++) {
                    int bi = (n >> 1) * 4 + (n & 1);
                    uint32_t fh[2] = {bh[bi], bh[bi + 2]};
                    uint32_t fl[2] = {bl[bi], bl[bi + 2]};
                    mma16816(acc[m][n], ah, fh);
                    mma16816(acc[m][n], ah, fl);
                    mma16816(acc[m][n], al, fh);
                }
            }
        }
        __syncthreads();
    }

    int g = lane >> 2, c2 = lane & 3;
    #pragma unroll
    for (int m = 0; m < 4; m++) {
        #pragma unroll
        for (int n = 0; n < 4; n++) {
            int col = k0 + wn + n * 8 + c2 * 2;
            #pragma unroll
            for (int h2 = 0; h2 < 2; h2++) {
                int rr = q0 + wm + m * 16 + g + h2 * 8;
                size_t idx = (size_t)i * QKSZ + (size_t)rr * W_DIM + col;
                float vx = acc[m][n][h2 * 2 + 0] * QK_SCALE + b0[idx] + b1[idx];
                float vy = acc[m][n][h2 * 2 + 1] * QK_SCALE + b0[idx + 1] + b1[idx + 1];
                if (b2) { vx += b2[idx]; vy += b2[idx + 1]; }
                *(float2*)(out + idx) = make_float2(vx, vy);
            }
        }
    }
}

// ---------------------------- softmax rowstats -----------------------------
__global__ __launch_bounds__(256)
void rowstats_kernel(const float* __restrict__ qk, float* __restrict__ rm,
                     float* __restrict__ rs)
{
    int row  = blockIdx.x * 8 + (threadIdx.x >> 5);
    int lane = threadIdx.x & 31;
    const float4* p = (const float4*)(qk + (size_t)row * W_DIM);
    float4 vals[4];
    float mx = -1e30f;
    #pragma unroll
    for (int j = 0; j < 4; j++) {
        float4 v = p[lane + j * 32];
        vals[j] = v;
        mx = fmaxf(mx, fmaxf(fmaxf(v.x, v.y), fmaxf(v.z, v.w)));
    }
    #pragma unroll
    for (int o = 16; o > 0; o >>= 1)
        mx = fmaxf(mx, __shfl_xor_sync(0xffffffffu, mx, o));
    float s = 0.f;
    #pragma unroll
    for (int j = 0; j < 4; j++) {
        float4 v = vals[j];
        s += exp2f((v.x - mx) * LOG2E) + exp2f((v.y - mx) * LOG2E)
           + exp2f((v.z - mx) * LOG2E) + exp2f((v.w - mx) * LOG2E);
    }
    #pragma unroll
    for (int o = 16; o > 0; o >>= 1)
        s += __shfl_xor_sync(0xffffffffu, s, o);
    if (lane == 0) { rm[row] = mx; rs[row] = 1.f / s; }
}

// ------------------------- AV GEMM via mma.sync ----------------------------
// att[i*128+dd][q] = sum_k softmax(qk)[q,k] * V[dd,k]
// K = 512 -> SIXTEEN 32-wide chunks (R14 bug: only ran 4).
// V via cp.async 2-deep ring; P prefetched one chunk ahead into registers.
__global__ __launch_bounds__(256)
void av_mma_kernel(const float* __restrict__ qk, const float* __restrict__ rm,
                   const float* __restrict__ rs,
                   const __nv_bfloat16* __restrict__ vh,
                   const __nv_bfloat16* __restrict__ vl,
                   float* __restrict__ att)
{
    extern __shared__ __nv_bfloat16 dsm[];
    int i = blockIdx.y, q0 = blockIdx.x << 7;
    int t = threadIdx.x, wid = t >> 5, lane = t & 31;
    int wm = (wid >> 2) * 64, wn = (wid & 3) * 32;

    const float* qkb = qk + (size_t)i * QKSZ;
    const __nv_bfloat16* vhb = vh + (size_t)i * 128 * W_DIM;
    const __nv_bfloat16* vlb = vl + (size_t)i * 128 * W_DIM;
    float* attb = att + (size_t)i * 128 * W_DIM;

    int prow = t >> 1, pch = (t & 1) * 16;
    float mrow = rm[i * W_DIM + q0 + prow];
    float srow = rs[i * W_DIM + q0 + prow];
    const float4* prows = (const float4*)(qkb + (size_t)(q0 + prow) * W_DIM + pch);

    auto issueV = [&](int c, int buf) {
        if (t < 128) {
            uint32_t sh = smem_u32(dsm + (size_t)(buf * 4 + 2) * MMA_ASZ + t * 40);
            uint32_t sl = smem_u32(dsm + (size_t)(buf * 4 + 3) * MMA_ASZ + t * 40);
            const __nv_bfloat16* gh = vhb + (size_t)t * W_DIM + c * 32;
            const __nv_bfloat16* gl = vlb + (size_t)t * W_DIM + c * 32;
            #pragma unroll
            for (int j = 0; j < 4; j++) {
                cp16(sh + j * 16, gh + j * 8);
                cp16(sl + j * 16, gl + j * 8);
            }
        }
        CP_COMMIT();
    };

    float acc[4][4][4];
    #pragma unroll
    for (int m = 0; m < 4; m++)
        #pragma unroll
        for (int n = 0; n < 4; n++)
            #pragma unroll
            for (int r = 0; r < 4; r++) acc[m][n][r] = 0.f;

    float4 pr[4];
    #pragma unroll
    for (int j = 0; j < 4; j++) pr[j] = prows[j];   // chunk 0
    issueV(0, 0);

    for (int c = 0; c < 16; c++) {                  // K = 512 -> 16 chunks
        // exp/split/STS P for chunk c (from regs loaded last iteration)
        {
            union { uint4 u[2]; __nv_bfloat16 h[16]; } H, L;
            #pragma unroll
            for (int j = 0; j < 4; j++) {
                float e[4];
                e[0] = exp2f((pr[j].x - mrow) * LOG2E) * srow;
                e[1] = exp2f((pr[j].y - mrow) * LOG2E) * srow;
                e[2] = exp2f((pr[j].z - mrow) * LOG2E) * srow;
                e[3] = exp2f((pr[j].w - mrow) * LOG2E) * srow;
                #pragma unroll
                for (int x2 = 0; x2 < 4; x2++) {
                    __nv_bfloat16 hh = __float2bfloat16(e[x2]);
                    H.h[j * 4 + x2] = hh;
                    L.h[j * 4 + x2] = __float2bfloat16(e[x2] - __bfloat162float(hh));
                }
            }
            __nv_bfloat16* ph = dsm + (size_t)((c & 1) * 4 + 0) * MMA_ASZ + prow * 40 + pch;
            __nv_bfloat16* pl = dsm + (size_t)((c & 1) * 4 + 1) * MMA_ASZ + prow * 40 + pch;
            *(uint4*)ph       = H.u[0];
            *(uint4*)(ph + 8) = H.u[1];
            *(uint4*)pl       = L.u[0];
            *(uint4*)(pl + 8) = L.u[1];
        }
        if (c < 15) {
            #pragma unroll
            for (int j = 0; j < 4; j++) pr[j] = prows[(c + 1) * 8 + j];
            issueV(c + 1, (c + 1) & 1);
            CP_WAIT1();
        } else {
            CP_WAIT0();
        }
        __syncthreads();
        __nv_bfloat16 (*sPh)[40] = (__nv_bfloat16(*)[40])(dsm + (size_t)((c & 1) * 4 + 0) * MMA_ASZ);
        __nv_bfloat16 (*sPl)[40] = (__nv_bfloat16(*)[40])(dsm + (size_t)((c & 1) * 4 + 1) * MMA_ASZ);
        __nv_bfloat16 (*sVh)[40] = (__nv_bfloat16(*)[40])(dsm + (size_t)((c & 1) * 4 + 2) * MMA_ASZ);
        __nv_bfloat16 (*sVl)[40] = (__nv_bfloat16(*)[40])(dsm + (size_t)((c & 1) * 4 + 3) * MMA_ASZ);
        #pragma unroll
        for (int kk = 0; kk < 32; kk += 16) {
            int arow = lane & 15;
            int ac = kk + (lane >> 4) * 8;
            uint32_t bh[8], bl[8];
            ldsm4(bh,     smem_u32(&sVh[wn + arow][ac]));
            ldsm4(bh + 4, smem_u32(&sVh[wn + 16 + arow][ac]));
            ldsm4(bl,     smem_u32(&sVl[wn + arow][ac]));
            ldsm4(bl + 4, smem_u32(&sVl[wn + 16 + arow][ac]));
            #pragma unroll
            for (int m = 0; m < 4; m++) {
                uint32_t ah[4], al[4];
                ldsm4(ah, smem_u32(&sPh[wm + m * 16 + arow][ac]));
                ldsm4(al, smem_u32(&sPl[wm + m * 16 + arow][ac]));
                #pragma unroll
                for (int n = 0; n < 4; n++) {
                    int bi = (n >> 1) * 4 + (n & 1);
                    uint32_t fh[2] = {bh[bi], bh[bi + 2]};
                    uint32_t fl[2] = {bl[bi], bl[bi + 2]};
                    mma16816(acc[m][n], ah, fh);
                    mma16816(acc[m][n], ah, fl);
                    mma16816(acc[m][n], al, fh);
                }
            }
        }
        __syncthreads();
    }

    int g = lane >> 2, c2 = lane & 3;
    #pragma unroll
    for (int m = 0; m < 4; m++) {
        #pragma unroll
        for (int n = 0; n < 4; n++) {
            int dd = wn + n * 8 + c2 * 2;
            #pragma unroll
            for (int h2 = 0; h2 < 2; h2++) {
                int rr = q0 + wm + m * 16 + g + h2 * 8;
                attb[(size_t)dd * W_DIM + rr]       = acc[m][n][h2 * 2 + 0];
                attb[(size_t)(dd + 1) * W_DIM + rr] = acc[m][n][h2 * 2 + 1];
            }
        }
    }
}

// --------------------- 3x3 conv 24->32 + SquaredReLU -----------------------
__global__ __launch_bounds__(256)
void conv3x3_sq_kernel(const float* __restrict__ in, const float* __restrict__ wgt,
                       float* __restrict__ out)
{
    __shared__ __align__(16) float ws[216 * 32];
    for (int e = threadIdx.x; e < 216 * 32; e += 256) {
        int o = e & 31, idx = e >> 5;
        ws[e] = wgt[o * 216 + idx];
    }
    __syncthreads();

    int p = blockIdx.x * 256 + threadIdx.x;
    int f = p >> 9, w = p & 511;
    float acc[32];
    #pragma unroll
    for (int o = 0; o < 32; o++) acc[o] = 0.f;

    for (int ic = 0; ic < 24; ic++) {
        #pragma unroll
        for (int ky = 0; ky < 3; ky++) {
            int ff = f + ky - 1;
            if ((unsigned)ff >= (unsigned)F_DIM) continue;
            const float* rp = in + (ic * F_DIM + ff) * W_DIM;
            #pragma unroll
            for (int kx = 0; kx < 3; kx++) {
                int ww = w + kx - 1;
                if ((unsigned)ww >= (unsigned)W_DIM) continue;
                float v = rp[ww];
                const float4* wp = (const float4*)&ws[(ic * 9 + ky * 3 + kx) * 32];
                #pragma unroll
                for (int o4 = 0; o4 < 8; o4++) {
                    float4 wv = wp[o4];
                    acc[o4 * 4 + 0] = fmaf(v, wv.x, acc[o4 * 4 + 0]);
                    acc[o4 * 4 + 1] = fmaf(v, wv.y, acc[o4 * 4 + 1]);
                    acc[o4 * 4 + 2] = fmaf(v, wv.z, acc[o4 * 4 + 2]);
                    acc[o4 * 4 + 3] = fmaf(v, wv.w, acc[o4 * 4 + 3]);
                }
            }
        }
    }
    #pragma unroll
    for (int o = 0; o < 32; o++) {
        float r = fmaxf(acc[o], 0.f);
        out[(o * F_DIM + f) * W_DIM + w] = r * r;
    }
}

// --------------------- 3x3 conv 32->8 + residual ---------------------------
__global__ __launch_bounds__(256)
void conv3x3_res_kernel(const float* __restrict__ in, const float* __restrict__ wgt,
                        const float* __restrict__ xin, float* __restrict__ out)
{
    __shared__ __align__(16) float ws[288 * 8];
    for (int e = threadIdx.x; e < 288 * 8; e += 256) {
        int o = e & 7, idx = e >> 3;
        ws[e] = wgt[o * 288 + idx];
    }
    __syncthreads();

    int p = blockIdx.x * 256 + threadIdx.x;
    int f = p >> 9, w = p & 511;
    float acc[8] = {0.f, 0.f, 0.f, 0.f, 0.f, 0.f, 0.f, 0.f};

    for (int ic = 0; ic < 32; ic++) {
        #pragma unroll
        for (int ky = 0; ky < 3; ky++) {
            int ff = f + ky - 1;
            if ((unsigned)ff >= (unsigned)F_DIM) continue;
            const float* rp = in + (ic * F_DIM + ff) * W_DIM;
            #pragma unroll
            for (int kx = 0; kx < 3; kx++) {
                int ww = w + kx - 1;
                if ((unsigned)ww >= (unsigned)W_DIM) continue;
                float v = rp[ww];
                const float4* wp = (const float4*)&ws[(ic * 9 + ky * 3 + kx) * 8];
                float4 w0 = wp[0], w1 = wp[1];
                acc[0] = fmaf(v, w0.x, acc[0]);
                acc[1] = fmaf(v, w0.y, acc[1]);
                acc[2] = fmaf(v, w0.z, acc[2]);
                acc[3] = fmaf(v, w0.w, acc[3]);
                acc[4] = fmaf(v, w1.x, acc[4]);
                acc[5] = fmaf(v, w1.y, acc[5]);
                acc[6] = fmaf(v, w1.z, acc[6]);
                acc[7] = fmaf(v, w1.w, acc[7]);
            }
        }
    }
    #pragma unroll
    for (int o = 0; o < 8; o++) {
        int idx = (o * F_DIM + f) * W_DIM + w;
        out[idx] = xin[idx] + acc[o];
    }
}

// ------------------------------- launcher ----------------------------------
extern "C" void kernel_launch(void* const* d_in, const int* in_sizes, int n_in,
                              void* d_out, int out_size)
{
    (void)in_sizes; (void)n_in; (void)out_size;

    const float* x        = (const float*)d_in[0];
    const float* skip     = (const float*)d_in[1];
    const float* prev_qk1 = (const float*)d_in[2];
    const float* prev_qk2 = (const float*)d_in[3];
    const float* skip_qk  = (const float*)d_in[4];
    const float* g1  = (const float*)d_in[5];
    const float* b1  = (const float*)d_in[6];
    const float* wq1 = (const float*)d_in[7];
    const float* wk1 = (const float*)d_in[8];
    const float* wv1 = (const float*)d_in[9];
    const float* wo1 = (const float*)d_in[10];
    const float* g2  = (const float*)d_in[11];
    const float* b2  = (const float*)d_in[12];
    const float* wq2 = (const float*)d_in[13];
    const float* wk2 = (const float*)d_in[14];
    const float* wv2 = (const float*)d_in[15];
    const float* wo2 = (const float*)d_in[16];
    const float* g3  = (const float*)d_in[17];
    const float* b3  = (const float*)d_in[18];
    const float* wc1 = (const float*)d_in[19];
    const float* wc2 = (const float*)d_in[20];

    float* out0 = (float*)d_out;
    float* opq1 = out0 + 8 * FW;
    float* opq2 = opq1 + (size_t)NINST * QKSZ;

    float *nx, *q, *k, *att, *z1, *z2, *nh, *n3, *tb, *rm, *rs;
    __nv_bfloat16 *qth, *qtl, *kth, *ktl, *vh, *vl;
    cudaGetSymbolAddress((void**)&nx,  g_nx);
    cudaGetSymbolAddress((void**)&q,   g_q);
    cudaGetSymbolAddress((void**)&k,   g_k);
    cudaGetSymbolAddress((void**)&att, g_att);
    cudaGetSymbolAddress((void**)&z1,  g_z1);
    cudaGetSymbolAddress((void**)&z2,  g_z2);
    cudaGetSymbolAddress((void**)&nh,  g_nh);
    cudaGetSymbolAddress((void**)&n3,  g_n3);
    cudaGetSymbolAddress((void**)&tb,  g_t);
    cudaGetSymbolAddress((void**)&rm,  g_rm);
    cudaGetSymbolAddress((void**)&rs,  g_rs);
    cudaGetSymbolAddress((void**)&qth, g_qth);
    cudaGetSymbolAddress((void**)&qtl, g_qtl);
    cudaGetSymbolAddress((void**)&kth, g_kth);
    cudaGetSymbolAddress((void**)&ktl, g_ktl);
    cudaGetSymbolAddress((void**)&vh,  g_vh);
    cudaGetSymbolAddress((void**)&vl,  g_vl);

    cudaFuncSetAttribute(qk_mma_kernel,
                         cudaFuncAttributeMaxDynamicSharedMemorySize, MMA_SMEM);
    cudaFuncSetAttribute(av_mma_kernel,
                         cudaFuncAttributeMaxDynamicSharedMemorySize, MMA_SMEM);

    // ---- block 1: LN1 + self-attention on nx -----------------------------
    ln_kernel<<<dim3(4, 8), 128>>>(x, nullptr, nullptr, g1, b1, nx);           // 1
    conv1x3_multi<3, true><<<2048, 256>>>(nx, wq1, wk1, wv1,
                                          q, k, nullptr, vh, vl, 8);           // 2
    split_qk_kernel<<<dim3(16, 4, 128), dim3(32, 8)>>>(q, k,
                                          qth, qtl, kth, ktl);                 // 3
    qk_mma_kernel<<<dim3(4, 4, NINST), 256, MMA_SMEM>>>(qth, qtl, kth, ktl,
                                          prev_qk1, skip_qk, nullptr, opq1);   // 4 (profiled)
    rowstats_kernel<<<4096, 256>>>(opq1, rm, rs);                              // 5
    av_mma_kernel<<<dim3(4, NINST), 256, MMA_SMEM>>>(opq1, rm, rs, vh, vl, att); // 6
    conv1x3_multi<1, false><<<2048, 256>>>(att, wo1, nullptr, nullptr,
                                          z1, nullptr, nullptr,
                                          nullptr, nullptr, 8);                // 7

    // ---- block 2: LN2 on [x, z1] + cross-attention vs skip ---------------
    ln_kernel<<<dim3(4, 16), 128>>>(x, z1, nullptr, g2, b2, nh);               // 8
    conv1x3_multi<1, false><<<2048, 256>>>(nh, wq2, nullptr, nullptr,
                                          q, nullptr, nullptr,
                                          nullptr, nullptr, 16);               // 9
    conv1x3_multi<2, true><<<2048, 256>>>(skip, wk2, wv2, nullptr,
                                          k, nullptr, nullptr, vh, vl, 8);     // 10
    split_qk_kernel<<<dim3(16, 4, 128), dim3(32, 8)>>>(q, k,
                                          qth, qtl, kth, ktl);                 // 11
    qk_mma_kernel<<<dim3(4, 4, NINST), 256, MMA_SMEM>>>(qth, qtl, kth, ktl,
                                          skip_qk, opq1, prev_qk2, opq2);      // 12
    rowstats_kernel<<<4096, 256>>>(opq2, rm, rs);                              // 13
    av_mma_kernel<<<dim3(4, NINST), 256, MMA_SMEM>>>(opq2, rm, rs, vh, vl, att); // 14
    conv1x3_multi<1, false><<<2048, 256>>>(att, wo2, nullptr, nullptr,
                                          z2, nullptr, nullptr,
                                          nullptr, nullptr, 8);                // 15

    // ---- block 3: LN3 on [x, z1, z2] + conv MLP + residual ---------------
    ln_kernel<<<dim3(4, 24), 128>>>(x, z1, z2, g3, b3, n3);                    // 16
    conv3x3_sq_kernel<<<2048, 256>>>(n3, wc1, tb);                             // 17
    conv3x3_res_kernel<<<2048, 256>>>(tb, wc2, x, out0);                       // 18
}

// round 16
// speedup vs baseline: 1.7892x; 1.4951x over previous
#include <cuda_runtime.h>
#include <cuda_bf16.h>
#include <math.h>
#include <stdint.h>

// ---------------------------------------------------------------------------
// FrameTransformerDecoder — qk & av via split-bf16 mma.sync with cp.async
// double-buffered pipelines; convs fp32 SIMT.
// R16: ln_kernel re-gridded (16xC CTAs x 256 thr, smem-reduced) — was 4xC x 128
// with 2048-deep serial load chains on a near-idle chip.
// Shapes: B=1, C=8, OC=8, F=1024, W=512, H=8, d=128, EXP=4
// ---------------------------------------------------------------------------

#define F_DIM 1024
#define W_DIM 512
#define FW    (F_DIM * W_DIM)
#define NINST 64
#define QKSZ  (W_DIM * W_DIM)
#define LOG2E 1.4426950408889634f
#define QK_SCALE 0.0883883476483184f

#define MMA_ASZ   (128 * 40)             // elements per smem array (row stride 40)
#define MMA_SMEM  (2 * 4 * MMA_ASZ * 2)  // 2 bufs x 4 arrays x bytes = 81920

// ------------------------- scratch (device globals) ------------------------
__device__ float g_nx [8  * FW];
__device__ float g_q  [8  * FW];
__device__ float g_k  [8  * FW];
__device__ float g_att[8  * FW];
__device__ float g_z1 [8  * FW];
__device__ float g_z2 [8  * FW];
__device__ float g_nh [16 * FW];
__device__ float g_n3 [24 * FW];
__device__ float g_t  [32 * FW];
__device__ float g_rm [NINST * W_DIM];
__device__ float g_rs [NINST * W_DIM];
// split-bf16 transposed q/k: [inst][w(512)][dd(128)]
__device__ __nv_bfloat16 g_qth[NINST * W_DIM * 128];
__device__ __nv_bfloat16 g_qtl[NINST * W_DIM * 128];
__device__ __nv_bfloat16 g_kth[NINST * W_DIM * 128];
__device__ __nv_bfloat16 g_ktl[NINST * W_DIM * 128];
// split-bf16 v in natural layout [inst*128+dd][w]
__device__ __nv_bfloat16 g_vh [8 * FW];
__device__ __nv_bfloat16 g_vl [8 * FW];

// ------------------------------ PTX helpers --------------------------------
__device__ __forceinline__ uint32_t smem_u32(const void* p) {
    uint32_t a;
    asm("{ .reg .u64 tmp; cvta.to.shared.u64 tmp, %1; cvt.u32.u64 %0, tmp; }"
        : "=r"(a) : "l"(p));
    return a;
}
__device__ __forceinline__ void ldsm4(uint32_t* r, uint32_t addr) {
    asm volatile("ldmatrix.sync.aligned.m8n8.x4.shared.b16 {%0,%1,%2,%3}, [%4];"
        : "=r"(r[0]), "=r"(r[1]), "=r"(r[2]), "=r"(r[3]) : "r"(addr));
}
__device__ __forceinline__ void mma16816(float* d, const uint32_t* a, const uint32_t* b) {
    asm volatile(
        "mma.sync.aligned.m16n8k16.row.col.f32.bf16.bf16.f32 "
        "{%0,%1,%2,%3}, {%4,%5,%6,%7}, {%8,%9}, {%0,%1,%2,%3};"
        : "+f"(d[0]), "+f"(d[1]), "+f"(d[2]), "+f"(d[3])
        : "r"(a[0]), "r"(a[1]), "r"(a[2]), "r"(a[3]), "r"(b[0]), "r"(b[1]));
}
__device__ __forceinline__ void cp16(uint32_t s, const void* g) {
    asm volatile("cp.async.cg.shared.global [%0], [%1], 16;" :: "r"(s), "l"(g));
}
#define CP_COMMIT() asm volatile("cp.async.commit_group;" ::: "memory")
#define CP_WAIT1()  asm volatile("cp.async.wait_group 1;" ::: "memory")
#define CP_WAIT0()  asm volatile("cp.async.wait_group 0;" ::: "memory")

// ------------------------------ LayerNorm ----------------------------------
// grid = (W/32, C), block = 256 (32 w-lanes x 8 f-groups). Two reads of the
// input (reduce pass + normalize pass), smem reduction of the 8 partials.
__global__ __launch_bounds__(256)
void ln_kernel(const float* s0, const float* s1, const float* s2,
               const float* __restrict__ g, const float* __restrict__ b,
               float* __restrict__ out)
{
    __shared__ float ssum[8][32];
    __shared__ float ssq [8][32];

    int c  = blockIdx.y;
    int tx = threadIdx.x & 31;
    int fg = threadIdx.x >> 5;                 // 0..7
    int w  = blockIdx.x * 32 + tx;
    const float* src = (c < 8) ? (s0 + c * FW)
                     : (c < 16) ? (s1 + (c - 8) * FW)
                                : (s2 + (c - 16) * FW);
    const float* p = src + w;

    float sum = 0.f, sq = 0.f;
    int f0 = fg * 128;
    #pragma unroll 4
    for (int f = f0; f < f0 + 128; f++) {
        float v = p[f * W_DIM];
        sum += v;
        sq = fmaf(v, v, sq);
    }
    ssum[fg][tx] = sum;
    ssq [fg][tx] = sq;
    __syncthreads();

    float tsum = 0.f, tsq = 0.f;
    #pragma unroll
    for (int j = 0; j < 8; j++) { tsum += ssum[j][tx]; tsq += ssq[j][tx]; }
    float mu  = tsum * (1.f / 1024.f);
    float var = tsq * (1.f / 1024.f) - mu * mu;
    float inv = rsqrtf(var + 1e-8f);

    float* op = out + c * FW + w;
    const float* gp = g + c * F_DIM;
    const float* bp = b + c * F_DIM;
    #pragma unroll 4
    for (int f = f0; f < f0 + 128; f++) {
        float v = p[f * W_DIM];
        op[f * W_DIM] = (v - mu) * inv * gp[f] + bp[f];
    }
}

// -------------------- 1x3 conv, NOUT projections ---------------------------
template<int NOUT, bool SPLIT_LAST>
__global__ __launch_bounds__(256)
void conv1x3_multi(const float* __restrict__ in,
                   const float* __restrict__ w0, const float* __restrict__ w1,
                   const float* __restrict__ w2,
                   float* __restrict__ o0, float* __restrict__ o1,
                   float* __restrict__ o2,
                   __nv_bfloat16* __restrict__ vh,
                   __nv_bfloat16* __restrict__ vl, int IC)
{
    __shared__ float ws[NOUT][8 * 16 * 3];
    int nw = 8 * IC * 3;
    for (int e = threadIdx.x; e < nw; e += 256) {
        ws[0][e] = w0[e];
        if (NOUT > 1) ws[1][e] = w1[e];
        if (NOUT > 2) ws[2][e] = w2[e];
    }
    __syncthreads();

    int p = blockIdx.x * 256 + threadIdx.x;
    int f = p >> 9, w = p & 511;
    float acc[NOUT][8];
    #pragma unroll
    for (int n = 0; n < NOUT; n++)
        #pragma unroll
        for (int o = 0; o < 8; o++) acc[n][o] = 0.f;

    for (int ic = 0; ic < IC; ic++) {
        const float* bp = in + (ic * F_DIM + f) * W_DIM + w;
        float m = bp[0];
        float l = (w > 0)   ? bp[-1] : 0.f;
        float r = (w < 511) ? bp[1]  : 0.f;
        #pragma unroll
        for (int n = 0; n < NOUT; n++) {
            #pragma unroll
            for (int o = 0; o < 8; o++) {
                const float* wp = ws[n] + (o * IC + ic) * 3;
                acc[n][o] = fmaf(l, wp[0], acc[n][o]);
                acc[n][o] = fmaf(m, wp[1], acc[n][o]);
                acc[n][o] = fmaf(r, wp[2], acc[n][o]);
            }
        }
    }
    float* outs[3] = {o0, o1, o2};
    #pragma unroll
    for (int n = 0; n < NOUT; n++) {
        if (SPLIT_LAST && n == NOUT - 1) {
            #pragma unroll
            for (int o = 0; o < 8; o++) {
                float val = acc[n][o];
                __nv_bfloat16 h = __float2bfloat16(val);
                __nv_bfloat16 lo = __float2bfloat16(val - __bfloat162float(h));
                size_t idx = (size_t)(o * F_DIM + f) * W_DIM + w;
                vh[idx] = h;
                vl[idx] = lo;
            }
        } else {
            #pragma unroll
            for (int o = 0; o < 8; o++)
                outs[n][(o * F_DIM + f) * W_DIM + w] = acc[n][o];
        }
    }
}

// ------------- transpose + split fp32 -> bf16 hi/lo, q AND k ---------------
__global__ __launch_bounds__(256)
void split_qk_kernel(const float* __restrict__ qin, const float* __restrict__ kin,
                     __nv_bfloat16* __restrict__ qoh, __nv_bfloat16* __restrict__ qol,
                     __nv_bfloat16* __restrict__ koh, __nv_bfloat16* __restrict__ kol)
{
    __shared__ float tile[32][33];
    int z = blockIdx.z;
    int i = z & 63;
    bool isK = z >= 64;
    const float* in = isK ? kin : qin;
    __nv_bfloat16* oh = isK ? koh : qoh;
    __nv_bfloat16* ol = isK ? kol : qol;

    int w0 = blockIdx.x * 32, d0 = blockIdx.y * 32;
    int tx = threadIdx.x, ty = threadIdx.y;
    const float* ib = in + ((size_t)i * 128 + d0) * W_DIM + w0;
    #pragma unroll
    for (int j = ty; j < 32; j += 8)
        tile[j][tx] = ib[j * W_DIM + tx];
    __syncthreads();
    size_t ob = (size_t)i * (W_DIM * 128) + (size_t)w0 * 128 + d0;
    #pragma unroll
    for (int j = ty; j < 32; j += 8) {
        float x = tile[tx][j];
        __nv_bfloat16 h = __float2bfloat16(x);
        float hf = __bfloat162float(h);
        __nv_bfloat16 l = __float2bfloat16(x - hf);
        oh[ob + (size_t)j * 128 + tx] = h;
        ol[ob + (size_t)j * 128 + tx] = l;
    }
}

// ------------------------- QK GEMM via mma.sync ----------------------------
// out[i,q,k] = SCALE * sum_d Q[q,d]*K[k,d] + b0 + b1 (+ b2)
// CTA 128q x 128k, 8 warps (2m x 4n), warp 64x32; cp.async 2-deep pipeline
// over four 32-d chunks. Dynamic smem: 2 bufs x {Qh,Ql,Kh,Kl} x 128x40 bf16.
__global__ __launch_bounds__(256)
void qk_mma_kernel(const __nv_bfloat16* __restrict__ qh, const __nv_bfloat16* __restrict__ ql,
                   const __nv_bfloat16* __restrict__ kh, const __nv_bfloat16* __restrict__ kl,
                   const float* __restrict__ b0, const float* __restrict__ b1,
                   const float* __restrict__ b2, float* __restrict__ out)
{
    extern __shared__ __nv_bfloat16 dsm[];
    int i = blockIdx.z, k0 = blockIdx.x << 7, q0 = blockIdx.y << 7;
    int t = threadIdx.x, wid = t >> 5, lane = t & 31;
    int wm = (wid >> 2) * 64, wn = (wid & 3) * 32;

    const __nv_bfloat16* qhg = qh + ((size_t)i * W_DIM + q0) * 128;
    const __nv_bfloat16* qlg = ql + ((size_t)i * W_DIM + q0) * 128;
    const __nv_bfloat16* khg = kh + ((size_t)i * W_DIM + k0) * 128;
    const __nv_bfloat16* klg = kl + ((size_t)i * W_DIM + k0) * 128;

    // staging role: t<128 -> Q row t; t>=128 -> K row t-128
    int row = t & 127;
    const __nv_bfloat16* gH = ((t < 128) ? qhg : khg) + (size_t)row * 128;
    const __nv_bfloat16* gL = ((t < 128) ? qlg : klg) + (size_t)row * 128;
    int whichH = (t < 128) ? 0 : 2;

    auto issue = [&](int c, int buf) {
        uint32_t sh = smem_u32(dsm + (size_t)(buf * 4 + whichH) * MMA_ASZ + row * 40);
        uint32_t sl = smem_u32(dsm + (size_t)(buf * 4 + whichH + 1) * MMA_ASZ + row * 40);
        const __nv_bfloat16* ghc = gH + c * 32;
        const __nv_bfloat16* glc = gL + c * 32;
        #pragma unroll
        for (int j = 0; j < 4; j++) {
            cp16(sh + j * 16, ghc + j * 8);
            cp16(sl + j * 16, glc + j * 8);
        }
        CP_COMMIT();
    };

    float acc[4][4][4];
    #pragma unroll
    for (int m = 0; m < 4; m++)
        #pragma unroll
        for (int n = 0; n < 4; n++)
            #pragma unroll
            for (int r = 0; r < 4; r++) acc[m][n][r] = 0.f;

    issue(0, 0);
    for (int c = 0; c < 4; c++) {      // d = 128 -> 4 chunks of 32
        if (c < 3) { issue(c + 1, (c + 1) & 1); CP_WAIT1(); }
        else       { CP_WAIT0(); }
        __syncthreads();
        __nv_bfloat16 (*sQh)[40] = (__nv_bfloat16(*)[40])(dsm + (size_t)((c & 1) * 4 + 0) * MMA_ASZ);
        __nv_bfloat16 (*sQl)[40] = (__nv_bfloat16(*)[40])(dsm + (size_t)((c & 1) * 4 + 1) * MMA_ASZ);
        __nv_bfloat16 (*sKh)[40] = (__nv_bfloat16(*)[40])(dsm + (size_t)((c & 1) * 4 + 2) * MMA_ASZ);
        __nv_bfloat16 (*sKl)[40] = (__nv_bfloat16(*)[40])(dsm + (size_t)((c & 1) * 4 + 3) * MMA_ASZ);
        #pragma unroll
        for (int kk = 0; kk < 32; kk += 16) {
            int arow = lane & 15;
            int ac = kk + (lane >> 4) * 8;
            uint32_t bh[8], bl[8];
            ldsm4(bh,     smem_u32(&sKh[wn + arow][ac]));
            ldsm4(bh + 4, smem_u32(&sKh[wn + 16 + arow][ac]));
            ldsm4(bl,     smem_u32(&sKl[wn + arow][ac]));
            ldsm4(bl + 4, smem_u32(&sKl[wn + 16 + arow][ac]));
            #pragma unroll
            for (int m = 0; m < 4; m++) {
                uint32_t ah[4], al[4];
                ldsm4(ah, smem_u32(&sQh[wm + m * 16 + arow][ac]));
                ldsm4(al, smem_u32(&sQl[wm + m * 16 + arow][ac]));
                #pragma unroll
                for (int n = 0; n < 4; n++) {
                    int bi = (n >> 1) * 4 + (n & 1);
                    uint32_t fh[2] = {bh[bi], bh[bi + 2]};
                    uint32_t fl[2] = {bl[bi], bl[bi + 2]};
                    mma16816(acc[m][n], ah, fh);
                    mma16816(acc[m][n], ah, fl);
                    mma16816(acc[m][n], al, fh);
                }
            }
        }
        __syncthreads();
    }

    int g = lane >> 2, c2 = lane & 3;
    #pragma unroll
    for (int m = 0; m < 4; m++) {
        #pragma unroll
        for (int n = 0; n < 4; n++) {
            int col = k0 + wn + n * 8 + c2 * 2;
            #pragma unroll
            for (int h2 = 0; h2 < 2; h2++) {
                int rr = q0 + wm + m * 16 + g + h2 * 8;
                size_t idx = (size_t)i * QKSZ + (size_t)rr * W_DIM + col;
                float vx = acc[m][n][h2 * 2 + 0] * QK_SCALE + b0[idx] + b1[idx];
                float vy = acc[m][n][h2 * 2 + 1] * QK_SCALE + b0[idx + 1] + b1[idx + 1];
                if (b2) { vx += b2[idx]; vy += b2[idx + 1]; }
                *(float2*)(out + idx) = make_float2(vx, vy);
            }
        }
    }
}

// ---------------------------- softmax rowstats -----------------------------
__global__ __launch_bounds__(256)
void rowstats_kernel(const float* __restrict__ qk, float* __restrict__ rm,
                     float* __restrict__ rs)
{
    int row  = blockIdx.x * 8 + (threadIdx.x >> 5);
    int lane = threadIdx.x & 31;
    const float4* p = (const float4*)(qk + (size_t)row * W_DIM);
    float4 vals[4];
    float mx = -1e30f;
    #pragma unroll
    for (int j = 0; j < 4; j++) {
        float4 v = p[lane + j * 32];
        vals[j] = v;
        mx = fmaxf(mx, fmaxf(fmaxf(v.x, v.y), fmaxf(v.z, v.w)));
    }
    #pragma unroll
    for (int o = 16; o > 0; o >>= 1)
        mx = fmaxf(mx, __shfl_xor_sync(0xffffffffu, mx, o));
    float s = 0.f;
    #pragma unroll
    for (int j = 0; j < 4; j++) {
        float4 v = vals[j];
        s += exp2f((v.x - mx) * LOG2E) + exp2f((v.y - mx) * LOG2E)
           + exp2f((v.z - mx) * LOG2E) + exp2f((v.w - mx) * LOG2E);
    }
    #pragma unroll
    for (int o = 16; o > 0; o >>= 1)
        s += __shfl_xor_sync(0xffffffffu, s, o);
    if (lane == 0) { rm[row] = mx; rs[row] = 1.f / s; }
}

// ------------------------- AV GEMM via mma.sync ----------------------------
// att[i*128+dd][q] = sum_k softmax(qk)[q,k] * V[dd,k]; K = 512 -> 16 chunks.
// V via cp.async 2-deep ring; P prefetched one chunk ahead into registers.
__global__ __launch_bounds__(256)
void av_mma_kernel(const float* __restrict__ qk, const float* __restrict__ rm,
                   const float* __restrict__ rs,
                   const __nv_bfloat16* __restrict__ vh,
                   const __nv_bfloat16* __restrict__ vl,
                   float* __restrict__ att)
{
    extern __shared__ __nv_bfloat16 dsm[];
    int i = blockIdx.y, q0 = blockIdx.x << 7;
    int t = threadIdx.x, wid = t >> 5, lane = t & 31;
    int wm = (wid >> 2) * 64, wn = (wid & 3) * 32;

    const float* qkb = qk + (size_t)i * QKSZ;
    const __nv_bfloat16* vhb = vh + (size_t)i * 128 * W_DIM;
    const __nv_bfloat16* vlb = vl + (size_t)i * 128 * W_DIM;
    float* attb = att + (size_t)i * 128 * W_DIM;

    int prow = t >> 1, pch = (t & 1) * 16;
    float mrow = rm[i * W_DIM + q0 + prow];
    float srow = rs[i * W_DIM + q0 + prow];
    const float4* prows = (const float4*)(qkb + (size_t)(q0 + prow) * W_DIM + pch);

    auto issueV = [&](int c, int buf) {
        if (t < 128) {
            uint32_t sh = smem_u32(dsm + (size_t)(buf * 4 + 2) * MMA_ASZ + t * 40);
            uint32_t sl = smem_u32(dsm + (size_t)(buf * 4 + 3) * MMA_ASZ + t * 40);
            const __nv_bfloat16* gh = vhb + (size_t)t * W_DIM + c * 32;
            const __nv_bfloat16* gl = vlb + (size_t)t * W_DIM + c * 32;
            #pragma unroll
            for (int j = 0; j < 4; j++) {
                cp16(sh + j * 16, gh + j * 8);
                cp16(sl + j * 16, gl + j * 8);
            }
        }
        CP_COMMIT();
    };

    float acc[4][4][4];
    #pragma unroll
    for (int m = 0; m < 4; m++)
        #pragma unroll
        for (int n = 0; n < 4; n++)
            #pragma unroll
            for (int r = 0; r < 4; r++) acc[m][n][r] = 0.f;

    float4 pr[4];
    #pragma unroll
    for (int j = 0; j < 4; j++) pr[j] = prows[j];   // chunk 0
    issueV(0, 0);

    for (int c = 0; c < 16; c++) {                  // K = 512 -> 16 chunks
        {
            union { uint4 u[2]; __nv_bfloat16 h[16]; } H, L;
            #pragma unroll
            for (int j = 0; j < 4; j++) {
                float e[4];
                e[0] = exp2f((pr[j].x - mrow) * LOG2E) * srow;
                e[1] = exp2f((pr[j].y - mrow) * LOG2E) * srow;
                e[2] = exp2f((pr[j].z - mrow) * LOG2E) * srow;
                e[3] = exp2f((pr[j].w - mrow) * LOG2E) * srow;
                #pragma unroll
                for (int x2 = 0; x2 < 4; x2++) {
                    __nv_bfloat16 hh = __float2bfloat16(e[x2]);
                    H.h[j * 4 + x2] = hh;
                    L.h[j * 4 + x2] = __float2bfloat16(e[x2] - __bfloat162float(hh));
                }
            }
            __nv_bfloat16* ph = dsm + (size_t)((c & 1) * 4 + 0) * MMA_ASZ + prow * 40 + pch;
            __nv_bfloat16* pl = dsm + (size_t)((c & 1) * 4 + 1) * MMA_ASZ + prow * 40 + pch;
            *(uint4*)ph       = H.u[0];
            *(uint4*)(ph + 8) = H.u[1];
            *(uint4*)pl       = L.u[0];
            *(uint4*)(pl + 8) = L.u[1];
        }
        if (c < 15) {
            #pragma unroll
            for (int j = 0; j < 4; j++) pr[j] = prows[(c + 1) * 8 + j];
            issueV(c + 1, (c + 1) & 1);
            CP_WAIT1();
        } else {
            CP_WAIT0();
        }
        __syncthreads();
        __nv_bfloat16 (*sPh)[40] = (__nv_bfloat16(*)[40])(dsm + (size_t)((c & 1) * 4 + 0) * MMA_ASZ);
        __nv_bfloat16 (*sPl)[40] = (__nv_bfloat16(*)[40])(dsm + (size_t)((c & 1) * 4 + 1) * MMA_ASZ);
        __nv_bfloat16 (*sVh)[40] = (__nv_bfloat16(*)[40])(dsm + (size_t)((c & 1) * 4 + 2) * MMA_ASZ);
        __nv_bfloat16 (*sVl)[40] = (__nv_bfloat16(*)[40])(dsm + (size_t)((c & 1) * 4 + 3) * MMA_ASZ);
        #pragma unroll
        for (int kk = 0; kk < 32; kk += 16) {
            int arow = lane & 15;
            int ac = kk + (lane >> 4) * 8;
            uint32_t bh[8], bl[8];
            ldsm4(bh,     smem_u32(&sVh[wn + arow][ac]));
            ldsm4(bh + 4, smem_u32(&sVh[wn + 16 + arow][ac]));
            ldsm4(bl,     smem_u32(&sVl[wn + arow][ac]));
            ldsm4(bl + 4, smem_u32(&sVl[wn + 16 + arow][ac]));
            #pragma unroll
            for (int m = 0; m < 4; m++) {
                uint32_t ah[4], al[4];
                ldsm4(ah, smem_u32(&sPh[wm + m * 16 + arow][ac]));
                ldsm4(al, smem_u32(&sPl[wm + m * 16 + arow][ac]));
                #pragma unroll
                for (int n = 0; n < 4; n++) {
                    int bi = (n >> 1) * 4 + (n & 1);
                    uint32_t fh[2] = {bh[bi], bh[bi + 2]};
                    uint32_t fl[2] = {bl[bi], bl[bi + 2]};
                    mma16816(acc[m][n], ah, fh);
                    mma16816(acc[m][n], ah, fl);
                    mma16816(acc[m][n], al, fh);
                }
            }
        }
        __syncthreads();
    }

    int g = lane >> 2, c2 = lane & 3;
    #pragma unroll
    for (int m = 0; m < 4; m++) {
        #pragma unroll
        for (int n = 0; n < 4; n++) {
            int dd = wn + n * 8 + c2 * 2;
            #pragma unroll
            for (int h2 = 0; h2 < 2; h2++) {
                int rr = q0 + wm + m * 16 + g + h2 * 8;
                attb[(size_t)dd * W_DIM + rr]       = acc[m][n][h2 * 2 + 0];
                attb[(size_t)(dd + 1) * W_DIM + rr] = acc[m][n][h2 * 2 + 1];
            }
        }
    }
}

// --------------------- 3x3 conv 24->32 + SquaredReLU -----------------------
__global__ __launch_bounds__(256)
void conv3x3_sq_kernel(const float* __restrict__ in, const float* __restrict__ wgt,
                       float* __restrict__ out)
{
    __shared__ __align__(16) float ws[216 * 32];
    for (int e = threadIdx.x; e < 216 * 32; e += 256) {
        int o = e & 31, idx = e >> 5;
        ws[e] = wgt[o * 216 + idx];
    }
    __syncthreads();

    int p = blockIdx.x * 256 + threadIdx.x;
    int f = p >> 9, w = p & 511;
    float acc[32];
    #pragma unroll
    for (int o = 0; o < 32; o++) acc[o] = 0.f;

    for (int ic = 0; ic < 24; ic++) {
        #pragma unroll
        for (int ky = 0; ky < 3; ky++) {
            int ff = f + ky - 1;
            if ((unsigned)ff >= (unsigned)F_DIM) continue;
            const float* rp = in + (ic * F_DIM + ff) * W_DIM;
            #pragma unroll
            for (int kx = 0; kx < 3; kx++) {
                int ww = w + kx - 1;
                if ((unsigned)ww >= (unsigned)W_DIM) continue;
                float v = rp[ww];
                const float4* wp = (const float4*)&ws[(ic * 9 + ky * 3 + kx) * 32];
                #pragma unroll
                for (int o4 = 0; o4 < 8; o4++) {
                    float4 wv = wp[o4];
                    acc[o4 * 4 + 0] = fmaf(v, wv.x, acc[o4 * 4 + 0]);
                    acc[o4 * 4 + 1] = fmaf(v, wv.y, acc[o4 * 4 + 1]);
                    acc[o4 * 4 + 2] = fmaf(v, wv.z, acc[o4 * 4 + 2]);
                    acc[o4 * 4 + 3] = fmaf(v, wv.w, acc[o4 * 4 + 3]);
                }
            }
        }
    }
    #pragma unroll
    for (int o = 0; o < 32; o++) {
        float r = fmaxf(acc[o], 0.f);
        out[(o * F_DIM + f) * W_DIM + w] = r * r;
    }
}

// --------------------- 3x3 conv 32->8 + residual ---------------------------
__global__ __launch_bounds__(256)
void conv3x3_res_kernel(const float* __restrict__ in, const float* __restrict__ wgt,
                        const float* __restrict__ xin, float* __restrict__ out)
{
    __shared__ __align__(16) float ws[288 * 8];
    for (int e = threadIdx.x; e < 288 * 8; e += 256) {
        int o = e & 7, idx = e >> 3;
        ws[e] = wgt[o * 288 + idx];
    }
    __syncthreads();

    int p = blockIdx.x * 256 + threadIdx.x;
    int f = p >> 9, w = p & 511;
    float acc[8] = {0.f, 0.f, 0.f, 0.f, 0.f, 0.f, 0.f, 0.f};

    for (int ic = 0; ic < 32; ic++) {
        #pragma unroll
        for (int ky = 0; ky < 3; ky++) {
            int ff = f + ky - 1;
            if ((unsigned)ff >= (unsigned)F_DIM) continue;
            const float* rp = in + (ic * F_DIM + ff) * W_DIM;
            #pragma unroll
            for (int kx = 0; kx < 3; kx++) {
                int ww = w + kx - 1;
                if ((unsigned)ww >= (unsigned)W_DIM) continue;
                float v = rp[ww];
                const float4* wp = (const float4*)&ws[(ic * 9 + ky * 3 + kx) * 8];
                float4 w0 = wp[0], w1 = wp[1];
                acc[0] = fmaf(v, w0.x, acc[0]);
                acc[1] = fmaf(v, w0.y, acc[1]);
                acc[2] = fmaf(v, w0.z, acc[2]);
                acc[3] = fmaf(v, w0.w, acc[3]);
                acc[4] = fmaf(v, w1.x, acc[4]);
                acc[5] = fmaf(v, w1.y, acc[5]);
                acc[6] = fmaf(v, w1.z, acc[6]);
                acc[7] = fmaf(v, w1.w, acc[7]);
            }
        }
    }
    #pragma unroll
    for (int o = 0; o < 8; o++) {
        int idx = (o * F_DIM + f) * W_DIM + w;
        out[idx] = xin[idx] + acc[o];
    }
}

// ------------------------------- launcher ----------------------------------
extern "C" void kernel_launch(void* const* d_in, const int* in_sizes, int n_in,
                              void* d_out, int out_size)
{
    (void)in_sizes; (void)n_in; (void)out_size;

    const float* x        = (const float*)d_in[0];
    const float* skip     = (const float*)d_in[1];
    const float* prev_qk1 = (const float*)d_in[2];
    const float* prev_qk2 = (const float*)d_in[3];
    const float* skip_qk  = (const float*)d_in[4];
    const float* g1  = (const float*)d_in[5];
    const float* b1  = (const float*)d_in[6];
    const float* wq1 = (const float*)d_in[7];
    const float* wk1 = (const float*)d_in[8];
    const float* wv1 = (const float*)d_in[9];
    const float* wo1 = (const float*)d_in[10];
    const float* g2  = (const float*)d_in[11];
    const float* b2  = (const float*)d_in[12];
    const float* wq2 = (const float*)d_in[13];
    const float* wk2 = (const float*)d_in[14];
    const float* wv2 = (const float*)d_in[15];
    const float* wo2 = (const float*)d_in[16];
    const float* g3  = (const float*)d_in[17];
    const float* b3  = (const float*)d_in[18];
    const float* wc1 = (const float*)d_in[19];
    const float* wc2 = (const float*)d_in[20];

    float* out0 = (float*)d_out;
    float* opq1 = out0 + 8 * FW;
    float* opq2 = opq1 + (size_t)NINST * QKSZ;

    float *nx, *q, *k, *att, *z1, *z2, *nh, *n3, *tb, *rm, *rs;
    __nv_bfloat16 *qth, *qtl, *kth, *ktl, *vh, *vl;
    cudaGetSymbolAddress((void**)&nx,  g_nx);
    cudaGetSymbolAddress((void**)&q,   g_q);
    cudaGetSymbolAddress((void**)&k,   g_k);
    cudaGetSymbolAddress((void**)&att, g_att);
    cudaGetSymbolAddress((void**)&z1,  g_z1);
    cudaGetSymbolAddress((void**)&z2,  g_z2);
    cudaGetSymbolAddress((void**)&nh,  g_nh);
    cudaGetSymbolAddress((void**)&n3,  g_n3);
    cudaGetSymbolAddress((void**)&tb,  g_t);
    cudaGetSymbolAddress((void**)&rm,  g_rm);
    cudaGetSymbolAddress((void**)&rs,  g_rs);
    cudaGetSymbolAddress((void**)&qth, g_qth);
    cudaGetSymbolAddress((void**)&qtl, g_qtl);
    cudaGetSymbolAddress((void**)&kth, g_kth);
    cudaGetSymbolAddress((void**)&ktl, g_ktl);
    cudaGetSymbolAddress((void**)&vh,  g_vh);
    cudaGetSymbolAddress((void**)&vl,  g_vl);

    cudaFuncSetAttribute(qk_mma_kernel,
                         cudaFuncAttributeMaxDynamicSharedMemorySize, MMA_SMEM);
    cudaFuncSetAttribute(av_mma_kernel,
                         cudaFuncAttributeMaxDynamicSharedMemorySize, MMA_SMEM);

    // ---- block 1: LN1 + self-attention on nx -----------------------------
    ln_kernel<<<dim3(16, 8), 256>>>(x, nullptr, nullptr, g1, b1, nx);          // 1
    conv1x3_multi<3, true><<<2048, 256>>>(nx, wq1, wk1, wv1,
                                          q, k, nullptr, vh, vl, 8);           // 2
    split_qk_kernel<<<dim3(16, 4, 128), dim3(32, 8)>>>(q, k,
                                          qth, qtl, kth, ktl);                 // 3
    qk_mma_kernel<<<dim3(4, 4, NINST), 256, MMA_SMEM>>>(qth, qtl, kth, ktl,
                                          prev_qk1, skip_qk, nullptr, opq1);   // 4 (profiled)
    rowstats_kernel<<<4096, 256>>>(opq1, rm, rs);                              // 5
    av_mma_kernel<<<dim3(4, NINST), 256, MMA_SMEM>>>(opq1, rm, rs, vh, vl, att); // 6
    conv1x3_multi<1, false><<<2048, 256>>>(att, wo1, nullptr, nullptr,
                                          z1, nullptr, nullptr,
                                          nullptr, nullptr, 8);                // 7

    // ---- block 2: LN2 on [x, z1] + cross-attention vs skip ---------------
    ln_kernel<<<dim3(16, 16), 256>>>(x, z1, nullptr, g2, b2, nh);              // 8
    conv1x3_multi<1, false><<<2048, 256>>>(nh, wq2, nullptr, nullptr,
                                          q, nullptr, nullptr,
                                          nullptr, nullptr, 16);               // 9
    conv1x3_multi<2, true><<<2048, 256>>>(skip, wk2, wv2, nullptr,
                                          k, nullptr, nullptr, vh, vl, 8);     // 10
    split_qk_kernel<<<dim3(16, 4, 128), dim3(32, 8)>>>(q, k,
                                          qth, qtl, kth, ktl);                 // 11
    qk_mma_kernel<<<dim3(4, 4, NINST), 256, MMA_SMEM>>>(qth, qtl, kth, ktl,
                                          skip_qk, opq1, prev_qk2, opq2);      // 12
    rowstats_kernel<<<4096, 256>>>(opq2, rm, rs);                              // 13
    av_mma_kernel<<<dim3(4, NINST), 256, MMA_SMEM>>>(opq2, rm, rs, vh, vl, att); // 14
    conv1x3_multi<1, false><<<2048, 256>>>(att, wo2, nullptr, nullptr,
                                          z2, nullptr, nullptr,
                                          nullptr, nullptr, 8);                // 15

    // ---- block 3: LN3 on [x, z1, z2] + conv MLP + residual ---------------
    ln_kernel<<<dim3(16, 24), 256>>>(x, z1, z2, g3, b3, n3);                   // 16
    conv3x3_sq_kernel<<<2048, 256>>>(n3, wc1, tb);                             // 17
    conv3x3_res_kernel<<<2048, 256>>>(tb, wc2, x, out0);                       // 18
}